// round 1
// baseline (speedup 1.0000x reference)
#include <cuda_runtime.h>
#include <math.h>

// Problem constants
#define B_SZ   2
#define T_SEQ  2048
#define C_DIM  1024
#define NH     16
#define HDIM   64
#define N_TOK  (B_SZ * T_SEQ)   // 4096

// ---------------------------------------------------------------------------
// Scratch (device globals; runtime alloc is forbidden)
// ---------------------------------------------------------------------------
__device__ float g_ln_buf [N_TOK * C_DIM];        // LN output (reused for both LNs)
__device__ float g_qkv_buf[N_TOK * 3 * C_DIM];    // QKV
__device__ float g_y_buf  [N_TOK * C_DIM];        // attention output (merged heads)
__device__ float g_x2_buf [N_TOK * C_DIM];        // x after attention residual
__device__ float g_act_buf[N_TOK * 4 * C_DIM];    // GELU(fc) activations

__device__ __forceinline__ float gelu_tanh(float v) {
    float v3 = v * v * v;
    return 0.5f * v * (1.0f + tanhf(0.7978845608028654f * (v + 0.044715f * v3)));
}

// ---------------------------------------------------------------------------
// LayerNorm: one block per row (1024 floats), 256 threads, float4 per thread
// ---------------------------------------------------------------------------
__global__ __launch_bounds__(256) void ln_kernel(
    const float* __restrict__ x, const float* __restrict__ g,
    const float* __restrict__ b, float* __restrict__ out)
{
    __shared__ float red[8];
    int row = blockIdx.x;
    int tid = threadIdx.x;
    const float4* x4 = (const float4*)(x + row * C_DIM);
    float4 v = x4[tid];

    float s = v.x + v.y + v.z + v.w;
    #pragma unroll
    for (int o = 16; o; o >>= 1) s += __shfl_xor_sync(0xffffffffu, s, o);
    if ((tid & 31) == 0) red[tid >> 5] = s;
    __syncthreads();
    s = red[0] + red[1] + red[2] + red[3] + red[4] + red[5] + red[6] + red[7];
    float mu = s * (1.0f / C_DIM);

    float dx0 = v.x - mu, dx1 = v.y - mu, dx2 = v.z - mu, dx3 = v.w - mu;
    float q = dx0*dx0 + dx1*dx1 + dx2*dx2 + dx3*dx3;
    #pragma unroll
    for (int o = 16; o; o >>= 1) q += __shfl_xor_sync(0xffffffffu, q, o);
    __syncthreads();
    if ((tid & 31) == 0) red[tid >> 5] = q;
    __syncthreads();
    q = red[0] + red[1] + red[2] + red[3] + red[4] + red[5] + red[6] + red[7];
    float rs = rsqrtf(q * (1.0f / C_DIM) + 1e-5f);

    float4 gg = ((const float4*)g)[tid];
    float4 bb = ((const float4*)b)[tid];
    float4 o;
    o.x = dx0 * rs * gg.x + bb.x;
    o.y = dx1 * rs * gg.y + bb.y;
    o.z = dx2 * rs * gg.z + bb.z;
    o.w = dx3 * rs * gg.w + bb.w;
    ((float4*)(out + row * C_DIM))[tid] = o;
}

// ---------------------------------------------------------------------------
// SGEMM: out[M,N] = A[M,K] @ W[K,N] + bias (+res / gelu per EPI)
// BM=BN=128, BK=16, 256 threads, 8x8 per-thread tile.
// EPI: 0 = bias only, 1 = bias + residual, 2 = bias + gelu
// M,N multiples of 128; K multiple of 16 (true for all four GEMMs).
// ---------------------------------------------------------------------------
template<int EPI>
__global__ __launch_bounds__(256) void sgemm_kernel(
    const float* __restrict__ A, const float* __restrict__ W,
    const float* __restrict__ bias, const float* __restrict__ res,
    float* __restrict__ out, int M, int N, int K)
{
    __shared__ float As[16][128];
    __shared__ float Bs[16][128];

    int tid = threadIdx.x;
    int m0 = blockIdx.y * 128;
    int n0 = blockIdx.x * 128;
    int ty = tid >> 4, tx = tid & 15;

    float acc[8][8];
    #pragma unroll
    for (int i = 0; i < 8; i++)
        #pragma unroll
        for (int j = 0; j < 8; j++) acc[i][j] = 0.0f;

    for (int k0 = 0; k0 < K; k0 += 16) {
        #pragma unroll
        for (int i = 0; i < 2; i++) {
            int idx = tid + 256 * i;
            int ar = idx >> 2, ac = (idx & 3) << 2;
            float4 av = *(const float4*)(A + (m0 + ar) * K + k0 + ac);
            As[ac + 0][ar] = av.x;
            As[ac + 1][ar] = av.y;
            As[ac + 2][ar] = av.z;
            As[ac + 3][ar] = av.w;
            int br = idx >> 5, bc = (idx & 31) << 2;
            *(float4*)(&Bs[br][bc]) = *(const float4*)(W + (k0 + br) * N + n0 + bc);
        }
        __syncthreads();

        #pragma unroll
        for (int k = 0; k < 16; k++) {
            float4 a0 = *(float4*)(&As[k][ty * 8]);
            float4 a1 = *(float4*)(&As[k][ty * 8 + 4]);
            float4 b0 = *(float4*)(&Bs[k][tx * 8]);
            float4 b1 = *(float4*)(&Bs[k][tx * 8 + 4]);
            float a[8] = {a0.x, a0.y, a0.z, a0.w, a1.x, a1.y, a1.z, a1.w};
            float b[8] = {b0.x, b0.y, b0.z, b0.w, b1.x, b1.y, b1.z, b1.w};
            #pragma unroll
            for (int i = 0; i < 8; i++)
                #pragma unroll
                for (int j = 0; j < 8; j++)
                    acc[i][j] += a[i] * b[j];
        }
        __syncthreads();
    }

    #pragma unroll
    for (int i = 0; i < 8; i++) {
        int row = m0 + ty * 8 + i;
        #pragma unroll
        for (int jj = 0; jj < 2; jj++) {
            int col = n0 + tx * 8 + jj * 4;
            float4 bv = *(const float4*)(bias + col);
            float4 o;
            o.x = acc[i][jj * 4 + 0] + bv.x;
            o.y = acc[i][jj * 4 + 1] + bv.y;
            o.z = acc[i][jj * 4 + 2] + bv.z;
            o.w = acc[i][jj * 4 + 3] + bv.w;
            if (EPI == 1) {
                float4 rv = *(const float4*)(res + row * N + col);
                o.x += rv.x; o.y += rv.y; o.z += rv.z; o.w += rv.w;
            }
            if (EPI == 2) {
                o.x = gelu_tanh(o.x); o.y = gelu_tanh(o.y);
                o.z = gelu_tanh(o.z); o.w = gelu_tanh(o.w);
            }
            *(float4*)(out + row * N + col) = o;
        }
    }
}

// ---------------------------------------------------------------------------
// Flash attention (fp32, causal), HD=64, 64x64 tiles, 256 threads.
// qkv layout: row n = b*T + t, cols [0,C)=Q, [C,2C)=K, [2C,3C)=V, head h at h*64.
// y output: [B,T,C] with head h at col h*64.
// Shared layouts: Qs[d][r], Ks[d][c], Vs[c][d] (stride 68), Ps[c][r] (stride 65)
// ---------------------------------------------------------------------------
#define VS_STRIDE 68
#define PS_STRIDE 65

__global__ __launch_bounds__(256) void flash_kernel(
    const float* __restrict__ qkv, float* __restrict__ y)
{
    extern __shared__ float sm[];
    float* Qs = sm;                        // 64*64
    float* Ks = Qs + 64 * 64;              // 64*64
    float* Vs = Ks + 64 * 64;              // 64*VS_STRIDE
    float* Ps = Vs + 64 * VS_STRIDE;       // 64*PS_STRIDE
    float* alpha_s = Ps + 64 * PS_STRIDE;  // 64
    float* lsum_s  = alpha_s + 64;         // 64

    int tid = threadIdx.x;
    int bh = blockIdx.y;
    int bb = bh >> 4;
    int h  = bh & 15;
    int q0 = blockIdx.x * 64;
    const int C3 = 3 * C_DIM;
    const float scale = 0.125f;  // 1/sqrt(64)

    int rr = tid & 63;       // token-within-tile for loads
    int dchunk = tid >> 6;   // 0..3

    // Load Q tile transposed (scale folded in): Qs[d][r]
    const float* qbase = qkv + (bb * T_SEQ + q0) * C3 + h * HDIM;
    #pragma unroll
    for (int it = 0; it < 4; it++) {
        int d0 = dchunk * 16 + it * 4;
        float4 v = *(const float4*)(qbase + rr * C3 + d0);
        Qs[(d0 + 0) * 64 + rr] = v.x * scale;
        Qs[(d0 + 1) * 64 + rr] = v.y * scale;
        Qs[(d0 + 2) * 64 + rr] = v.z * scale;
        Qs[(d0 + 3) * 64 + rr] = v.w * scale;
    }

    int ty = tid >> 4, tx = tid & 15;   // compute-role mapping (4x4 tiles)
    int r_smax = tid >> 2;              // softmax-role row
    int csub   = tid & 3;               // softmax-role column subgroup

    float acc[4][4];
    #pragma unroll
    for (int i = 0; i < 4; i++)
        #pragma unroll
        for (int j = 0; j < 4; j++) acc[i][j] = 0.0f;

    float m_run = -1e30f;
    float l_run = 0.0f;

    for (int k0 = 0; k0 <= q0 + 63; k0 += 64) {
        __syncthreads();  // previous iteration done before overwriting K/V
        const float* kbase = qkv + (bb * T_SEQ + k0) * C3 + C_DIM + h * HDIM;
        const float* vbase = kbase + C_DIM;
        #pragma unroll
        for (int it = 0; it < 4; it++) {
            int d0 = dchunk * 16 + it * 4;
            float4 kv = *(const float4*)(kbase + rr * C3 + d0);
            Ks[(d0 + 0) * 64 + rr] = kv.x;
            Ks[(d0 + 1) * 64 + rr] = kv.y;
            Ks[(d0 + 2) * 64 + rr] = kv.z;
            Ks[(d0 + 3) * 64 + rr] = kv.w;
            float4 vv = *(const float4*)(vbase + rr * C3 + d0);
            *(float4*)(Vs + rr * VS_STRIDE + d0) = vv;
        }
        __syncthreads();

        // S = Q K^T (scaled), 4x4 per thread
        float s[4][4];
        #pragma unroll
        for (int i = 0; i < 4; i++)
            #pragma unroll
            for (int j = 0; j < 4; j++) s[i][j] = 0.0f;
        #pragma unroll 8
        for (int d = 0; d < 64; d++) {
            float4 qa = *(float4*)(Qs + d * 64 + ty * 4);
            float4 kb = *(float4*)(Ks + d * 64 + tx * 4);
            float aa[4] = {qa.x, qa.y, qa.z, qa.w};
            float bbv[4] = {kb.x, kb.y, kb.z, kb.w};
            #pragma unroll
            for (int i = 0; i < 4; i++)
                #pragma unroll
                for (int j = 0; j < 4; j++)
                    s[i][j] += aa[i] * bbv[j];
        }
        // causal mask + store transposed to Ps[c][r]
        #pragma unroll
        for (int i = 0; i < 4; i++) {
            int gr = q0 + ty * 4 + i;
            #pragma unroll
            for (int j = 0; j < 4; j++) {
                int gc = k0 + tx * 4 + j;
                float val = (gc <= gr) ? s[i][j] : -1e30f;
                Ps[(tx * 4 + j) * PS_STRIDE + (ty * 4 + i)] = val;
            }
        }
        __syncthreads();

        // Online softmax (4 threads per row, 16 cols each)
        float vals[16];
        float mt = -1e30f;
        #pragma unroll
        for (int k = 0; k < 16; k++) {
            vals[k] = Ps[(csub + 4 * k) * PS_STRIDE + r_smax];
            mt = fmaxf(mt, vals[k]);
        }
        mt = fmaxf(mt, __shfl_xor_sync(0xffffffffu, mt, 1));
        mt = fmaxf(mt, __shfl_xor_sync(0xffffffffu, mt, 2));
        float m_new = fmaxf(m_run, mt);
        float alpha = __expf(m_run - m_new);
        float sumloc = 0.0f;
        #pragma unroll
        for (int k = 0; k < 16; k++) {
            float p = __expf(vals[k] - m_new);
            Ps[(csub + 4 * k) * PS_STRIDE + r_smax] = p;
            sumloc += p;
        }
        sumloc += __shfl_xor_sync(0xffffffffu, sumloc, 1);
        sumloc += __shfl_xor_sync(0xffffffffu, sumloc, 2);
        l_run = l_run * alpha + sumloc;
        m_run = m_new;
        if (csub == 0) alpha_s[r_smax] = alpha;
        __syncthreads();

        // Rescale O, then O += P V
        #pragma unroll
        for (int i = 0; i < 4; i++) {
            float al = alpha_s[ty * 4 + i];
            #pragma unroll
            for (int j = 0; j < 4; j++) acc[i][j] *= al;
        }
        #pragma unroll 8
        for (int c = 0; c < 64; c++) {
            float p0 = Ps[c * PS_STRIDE + ty * 4 + 0];
            float p1 = Ps[c * PS_STRIDE + ty * 4 + 1];
            float p2 = Ps[c * PS_STRIDE + ty * 4 + 2];
            float p3 = Ps[c * PS_STRIDE + ty * 4 + 3];
            float4 vv = *(float4*)(Vs + c * VS_STRIDE + tx * 4);
            acc[0][0] += p0 * vv.x; acc[0][1] += p0 * vv.y; acc[0][2] += p0 * vv.z; acc[0][3] += p0 * vv.w;
            acc[1][0] += p1 * vv.x; acc[1][1] += p1 * vv.y; acc[1][2] += p1 * vv.z; acc[1][3] += p1 * vv.w;
            acc[2][0] += p2 * vv.x; acc[2][1] += p2 * vv.y; acc[2][2] += p2 * vv.z; acc[2][3] += p2 * vv.w;
            acc[3][0] += p3 * vv.x; acc[3][1] += p3 * vv.y; acc[3][2] += p3 * vv.z; acc[3][3] += p3 * vv.w;
        }
    }

    if (csub == 0) lsum_s[r_smax] = l_run;
    __syncthreads();

    #pragma unroll
    for (int i = 0; i < 4; i++) {
        float inv = 1.0f / lsum_s[ty * 4 + i];
        float4 o;
        o.x = acc[i][0] * inv;
        o.y = acc[i][1] * inv;
        o.z = acc[i][2] * inv;
        o.w = acc[i][3] * inv;
        int row = bb * T_SEQ + q0 + ty * 4 + i;
        *(float4*)(y + row * C_DIM + h * HDIM + tx * 4) = o;
    }
}

// ---------------------------------------------------------------------------
// Launch
// ---------------------------------------------------------------------------
extern "C" void kernel_launch(void* const* d_in, const int* in_sizes, int n_in,
                              void* d_out, int out_size)
{
    const float* x      = (const float*)d_in[0];
    const float* ln1_g  = (const float*)d_in[1];
    const float* ln1_b  = (const float*)d_in[2];
    const float* W_attn = (const float*)d_in[3];
    const float* b_attn = (const float*)d_in[4];
    const float* W_proj = (const float*)d_in[5];
    const float* b_proj = (const float*)d_in[6];
    const float* ln2_g  = (const float*)d_in[7];
    const float* ln2_b  = (const float*)d_in[8];
    const float* W_fc   = (const float*)d_in[9];
    const float* b_fc   = (const float*)d_in[10];
    const float* W_fc2  = (const float*)d_in[11];
    const float* b_fc2  = (const float*)d_in[12];
    float* out = (float*)d_out;

    float *g_ln, *g_qkv, *g_y, *g_x2, *g_act;
    cudaGetSymbolAddress((void**)&g_ln,  g_ln_buf);
    cudaGetSymbolAddress((void**)&g_qkv, g_qkv_buf);
    cudaGetSymbolAddress((void**)&g_y,   g_y_buf);
    cudaGetSymbolAddress((void**)&g_x2,  g_x2_buf);
    cudaGetSymbolAddress((void**)&g_act, g_act_buf);

    size_t fa_smem = (size_t)(64*64 + 64*64 + 64*VS_STRIDE + 64*PS_STRIDE + 128) * sizeof(float);
    cudaFuncSetAttribute(flash_kernel, cudaFuncAttributeMaxDynamicSharedMemorySize, (int)fa_smem);

    // 1. LN1
    ln_kernel<<<N_TOK, 256>>>(x, ln1_g, ln1_b, g_ln);
    // 2. QKV GEMM: [4096,1024] @ [1024,3072]
    sgemm_kernel<0><<<dim3(3 * C_DIM / 128, N_TOK / 128), 256>>>(
        g_ln, W_attn, b_attn, nullptr, g_qkv, N_TOK, 3 * C_DIM, C_DIM);
    // 3. Flash attention
    flash_kernel<<<dim3(T_SEQ / 64, B_SZ * NH), 256, fa_smem>>>(g_qkv, g_y);
    // 4. Proj GEMM + residual: x2 = x + y @ W_proj + b_proj
    sgemm_kernel<1><<<dim3(C_DIM / 128, N_TOK / 128), 256>>>(
        g_y, W_proj, b_proj, x, g_x2, N_TOK, C_DIM, C_DIM);
    // 5. LN2
    ln_kernel<<<N_TOK, 256>>>(g_x2, ln2_g, ln2_b, g_ln);
    // 6. FC GEMM + GELU: [4096,1024] @ [1024,4096]
    sgemm_kernel<2><<<dim3(4 * C_DIM / 128, N_TOK / 128), 256>>>(
        g_ln, W_fc, b_fc, nullptr, g_act, N_TOK, 4 * C_DIM, C_DIM);
    // 7. FC2 GEMM + residual: out = x2 + act @ W_fc2 + b_fc2
    sgemm_kernel<1><<<dim3(C_DIM / 128, N_TOK / 128), 256>>>(
        g_act, W_fc2, b_fc2, g_x2, out, N_TOK, C_DIM, 4 * C_DIM);
}

// round 3
// speedup vs baseline: 1.7314x; 1.7314x over previous
#include <cuda_runtime.h>
#include <cuda_bf16.h>
#include <math.h>
#include <stdint.h>

// Problem constants
#define B_SZ   2
#define T_SEQ  2048
#define C_DIM  1024
#define NH     16
#define HDIM   64
#define N_TOK  (B_SZ * T_SEQ)   // 4096

// ---------------------------------------------------------------------------
// Scratch (device globals; runtime alloc is forbidden)
// ---------------------------------------------------------------------------
__device__ float         g_qkv_buf[N_TOK * 3 * C_DIM];     // QKV fp32 (flash input)
__device__ float         g_x2_buf [N_TOK * C_DIM];         // x after attn residual
__device__ __nv_bfloat16 g_ah[N_TOK * C_DIM];              // LN out hi (reused LN1/LN2)
__device__ __nv_bfloat16 g_al[N_TOK * C_DIM];              // LN out lo
__device__ __nv_bfloat16 g_yh[N_TOK * C_DIM];              // attn out hi
__device__ __nv_bfloat16 g_yl[N_TOK * C_DIM];              // attn out lo
__device__ __nv_bfloat16 g_mh[N_TOK * 4 * C_DIM];          // gelu act hi
__device__ __nv_bfloat16 g_ml[N_TOK * 4 * C_DIM];          // gelu act lo
// Transposed + split weights: Wt[n*K + k] = W[k*N + n]
__device__ __nv_bfloat16 g_wattn_h[3 * C_DIM * C_DIM], g_wattn_l[3 * C_DIM * C_DIM];
__device__ __nv_bfloat16 g_wproj_h[C_DIM * C_DIM],     g_wproj_l[C_DIM * C_DIM];
__device__ __nv_bfloat16 g_wfc_h  [4 * C_DIM * C_DIM], g_wfc_l  [4 * C_DIM * C_DIM];
__device__ __nv_bfloat16 g_wfc2_h [C_DIM * 4 * C_DIM], g_wfc2_l [C_DIM * 4 * C_DIM];

// ---------------------------------------------------------------------------
// Helpers
// ---------------------------------------------------------------------------
__device__ __forceinline__ float gelu_tanh(float v) {
    float v3 = v * v * v;
    return 0.5f * v * (1.0f + tanhf(0.7978845608028654f * (v + 0.044715f * v3)));
}

__device__ __forceinline__ void split_bf16(float v, __nv_bfloat16& h, __nv_bfloat16& l) {
    h = __float2bfloat16(v);
    l = __float2bfloat16(v - __bfloat162float(h));
}

__device__ __forceinline__ uint32_t smem_u32(const void* p) {
    uint32_t a;
    asm("{ .reg .u64 t; cvta.to.shared.u64 t, %1; cvt.u32.u64 %0, t; }" : "=r"(a) : "l"(p));
    return a;
}

__device__ __forceinline__ void ldm_x4(uint32_t* r, uint32_t addr) {
    asm volatile("ldmatrix.sync.aligned.m8n8.x4.shared.b16 {%0,%1,%2,%3}, [%4];"
                 : "=r"(r[0]), "=r"(r[1]), "=r"(r[2]), "=r"(r[3]) : "r"(addr));
}

__device__ __forceinline__ void mma_bf16(float* c, const uint32_t* a, const uint32_t* b) {
    asm volatile(
        "mma.sync.aligned.m16n8k16.row.col.f32.bf16.bf16.f32 "
        "{%0,%1,%2,%3}, {%4,%5,%6,%7}, {%8,%9}, {%0,%1,%2,%3};"
        : "+f"(c[0]), "+f"(c[1]), "+f"(c[2]), "+f"(c[3])
        : "r"(a[0]), "r"(a[1]), "r"(a[2]), "r"(a[3]), "r"(b[0]), "r"(b[1]));
}

__device__ __forceinline__ void cp16(uint32_t saddr, const void* g) {
    asm volatile("cp.async.cg.shared.global [%0], [%1], 16;" :: "r"(saddr), "l"(g));
}
#define CP_COMMIT() asm volatile("cp.async.commit_group;")
#define CP_WAIT(n)  asm volatile("cp.async.wait_group %0;" :: "n"(n))

// smem tile geometry: 128 rows x 32 bf16, row stride 40 elems (80 B)
#define T_STRIDE   40
#define T_ROWB     80
#define T_BYTES    10240                 // 128 * 80
#define BUF_BYTES  (4 * T_BYTES)         // Ahi, Alo, Bhi, Blo
#define GEMM_SMEM  (2 * BUF_BYTES)       // 81920

// ---------------------------------------------------------------------------
// Weight transpose + hi/lo split:  W[K,N] fp32 -> Wt_hi/lo[N,K] bf16
// ---------------------------------------------------------------------------
__global__ __launch_bounds__(256) void transpose_split_kernel(
    const float* __restrict__ W, __nv_bfloat16* __restrict__ Th,
    __nv_bfloat16* __restrict__ Tl, int K, int N)
{
    __shared__ float t[32][33];
    int n0 = blockIdx.x * 32, k0 = blockIdx.y * 32;
    int tx = threadIdx.x, ty = threadIdx.y;   // 32 x 8
    #pragma unroll
    for (int i = 0; i < 4; i++)
        t[ty + 8 * i][tx] = W[(size_t)(k0 + ty + 8 * i) * N + n0 + tx];
    __syncthreads();
    #pragma unroll
    for (int i = 0; i < 4; i++) {
        float v = t[tx][ty + 8 * i];
        __nv_bfloat16 h, l;
        split_bf16(v, h, l);
        size_t o = (size_t)(n0 + ty + 8 * i) * K + k0 + tx;
        Th[o] = h;
        Tl[o] = l;
    }
}

// ---------------------------------------------------------------------------
// LayerNorm -> bf16 hi/lo split output
// ---------------------------------------------------------------------------
__global__ __launch_bounds__(256) void ln_kernel(
    const float* __restrict__ x, const float* __restrict__ g,
    const float* __restrict__ b, __nv_bfloat16* __restrict__ oh,
    __nv_bfloat16* __restrict__ ol)
{
    __shared__ float red[8];
    int row = blockIdx.x;
    int tid = threadIdx.x;
    const float4* x4 = (const float4*)(x + (size_t)row * C_DIM);
    float4 v = x4[tid];

    float s = v.x + v.y + v.z + v.w;
    #pragma unroll
    for (int o = 16; o; o >>= 1) s += __shfl_xor_sync(0xffffffffu, s, o);
    if ((tid & 31) == 0) red[tid >> 5] = s;
    __syncthreads();
    s = red[0] + red[1] + red[2] + red[3] + red[4] + red[5] + red[6] + red[7];
    float mu = s * (1.0f / C_DIM);

    float dx0 = v.x - mu, dx1 = v.y - mu, dx2 = v.z - mu, dx3 = v.w - mu;
    float q = dx0*dx0 + dx1*dx1 + dx2*dx2 + dx3*dx3;
    #pragma unroll
    for (int o = 16; o; o >>= 1) q += __shfl_xor_sync(0xffffffffu, q, o);
    __syncthreads();
    if ((tid & 31) == 0) red[tid >> 5] = q;
    __syncthreads();
    q = red[0] + red[1] + red[2] + red[3] + red[4] + red[5] + red[6] + red[7];
    float rs = rsqrtf(q * (1.0f / C_DIM) + 1e-5f);

    float4 gg = ((const float4*)g)[tid];
    float4 bb = ((const float4*)b)[tid];
    float o0 = dx0 * rs * gg.x + bb.x;
    float o1 = dx1 * rs * gg.y + bb.y;
    float o2 = dx2 * rs * gg.z + bb.z;
    float o3 = dx3 * rs * gg.w + bb.w;

    __nv_bfloat16 h0,h1,h2,h3,l0,l1,l2,l3;
    split_bf16(o0,h0,l0); split_bf16(o1,h1,l1);
    split_bf16(o2,h2,l2); split_bf16(o3,h3,l3);
    size_t base = (size_t)row * C_DIM + tid * 4;
    ((__nv_bfloat162*)(oh + base))[0] = __nv_bfloat162{h0, h1};
    ((__nv_bfloat162*)(oh + base))[1] = __nv_bfloat162{h2, h3};
    ((__nv_bfloat162*)(ol + base))[0] = __nv_bfloat162{l0, l1};
    ((__nv_bfloat162*)(ol + base))[1] = __nv_bfloat162{l2, l3};
}

// ---------------------------------------------------------------------------
// HMMA GEMM: D[M,N] = A[M,K] @ B[N,K]^T via 3-pass bf16 split (mma.sync).
// 128x128 CTA tile, BK=32, 8 warps (64x32 each), cp.async double buffer.
// EPI: 0 = fp32 out + bias; 1 = fp32 out + bias + res; 2 = gelu -> bf16 hi/lo
// ---------------------------------------------------------------------------
template<int EPI>
__global__ __launch_bounds__(256) void hmma_gemm(
    const __nv_bfloat16* __restrict__ Ahi, const __nv_bfloat16* __restrict__ Alo,
    const __nv_bfloat16* __restrict__ Bhi, const __nv_bfloat16* __restrict__ Blo,
    const float* __restrict__ bias, const float* __restrict__ res,
    float* __restrict__ outf, __nv_bfloat16* __restrict__ oh,
    __nv_bfloat16* __restrict__ ol, int M, int N, int K)
{
    extern __shared__ char smem[];
    uint32_t sb = smem_u32(smem);
    int tid = threadIdx.x, lane = tid & 31, w = tid >> 5;
    int wm = w >> 2, wn = w & 3;
    int m0 = blockIdx.y * 128, n0 = blockIdx.x * 128;

    const __nv_bfloat16* srcs[4] = {
        Ahi + (size_t)m0 * K, Alo + (size_t)m0 * K,
        Bhi + (size_t)n0 * K, Blo + (size_t)n0 * K };

    int r_ld = tid >> 2;            // 0..63? no: 0..? tid<256 -> r in 0..63 per u
    int c_ld = tid & 3;

    float acc[4][4][4];
    #pragma unroll
    for (int a = 0; a < 4; a++)
        #pragma unroll
        for (int b = 0; b < 4; b++)
            #pragma unroll
            for (int c = 0; c < 4; c++) acc[a][b][c] = 0.0f;

    const int nch = K >> 5;

    // stage chunk 0 into buf 0
    #pragma unroll
    for (int t = 0; t < 4; t++) {
        #pragma unroll
        for (int u = 0; u < 2; u++) {
            int idx = tid + 256 * u;
            int r = idx >> 2, c = idx & 3;
            cp16(sb + t * T_BYTES + r * T_ROWB + c * 16, srcs[t] + (size_t)r * K + c * 8);
        }
    }
    CP_COMMIT();

    for (int ch = 0; ch < nch; ch++) {
        uint32_t buf = sb + (ch & 1) * BUF_BYTES;
        if (ch + 1 < nch) {
            uint32_t nbuf = sb + ((ch + 1) & 1) * BUF_BYTES;
            int k0 = (ch + 1) << 5;
            #pragma unroll
            for (int t = 0; t < 4; t++) {
                #pragma unroll
                for (int u = 0; u < 2; u++) {
                    int idx = tid + 256 * u;
                    int r = idx >> 2, c = idx & 3;
                    cp16(nbuf + t * T_BYTES + r * T_ROWB + c * 16,
                         srcs[t] + (size_t)r * K + k0 + c * 8);
                }
            }
            CP_COMMIT();
            CP_WAIT(1);
        } else {
            CP_WAIT(0);
        }
        __syncthreads();

        uint32_t abase = buf;                 // Ahi; Alo at +T_BYTES
        uint32_t bbase = buf + 2 * T_BYTES;   // Bhi; Blo at +T_BYTES

        int arow = (lane & 7) + ((lane >> 3) & 1) * 8;
        int akof = ((lane >> 4) & 1) * 8;
        int brow = (lane & 7) + ((lane >> 4) & 1) * 8;
        int bkof = ((lane >> 3) & 1) * 8;

        #pragma unroll
        for (int ks = 0; ks < 2; ks++) {
            uint32_t Ah[4][4], Al[4][4], Bh[4][2], Bl[4][2];
            #pragma unroll
            for (int mf = 0; mf < 4; mf++) {
                uint32_t ad = abase + (uint32_t)(((wm * 64 + mf * 16 + arow) * T_STRIDE
                                                 + ks * 16 + akof) * 2);
                ldm_x4(Ah[mf], ad);
                ldm_x4(Al[mf], ad + T_BYTES);
            }
            #pragma unroll
            for (int np = 0; np < 2; np++) {
                uint32_t bd = bbase + (uint32_t)(((wn * 32 + np * 16 + brow) * T_STRIDE
                                                 + ks * 16 + bkof) * 2);
                uint32_t th[4], tl[4];
                ldm_x4(th, bd);
                ldm_x4(tl, bd + T_BYTES);
                Bh[np*2][0]=th[0]; Bh[np*2][1]=th[1]; Bh[np*2+1][0]=th[2]; Bh[np*2+1][1]=th[3];
                Bl[np*2][0]=tl[0]; Bl[np*2][1]=tl[1]; Bl[np*2+1][0]=tl[2]; Bl[np*2+1][1]=tl[3];
            }
            #pragma unroll
            for (int mf = 0; mf < 4; mf++)
                #pragma unroll
                for (int nf = 0; nf < 4; nf++)
                    mma_bf16(acc[mf][nf], Ah[mf], Bh[nf]);
            #pragma unroll
            for (int mf = 0; mf < 4; mf++)
                #pragma unroll
                for (int nf = 0; nf < 4; nf++)
                    mma_bf16(acc[mf][nf], Ah[mf], Bl[nf]);
            #pragma unroll
            for (int mf = 0; mf < 4; mf++)
                #pragma unroll
                for (int nf = 0; nf < 4; nf++)
                    mma_bf16(acc[mf][nf], Al[mf], Bh[nf]);
        }
        __syncthreads();
    }

    // Epilogue: acc -> global
    int qr = lane >> 2;             // 0..7
    int qc = (lane & 3) * 2;        // 0,2,4,6
    #pragma unroll
    for (int mf = 0; mf < 4; mf++) {
        #pragma unroll
        for (int nf = 0; nf < 4; nf++) {
            int col = n0 + wn * 32 + nf * 8 + qc;
            float b0 = bias[col], b1 = bias[col + 1];
            #pragma unroll
            for (int half = 0; half < 2; half++) {
                int row = m0 + wm * 64 + mf * 16 + qr + half * 8;
                float v0 = acc[mf][nf][half * 2 + 0] + b0;
                float v1 = acc[mf][nf][half * 2 + 1] + b1;
                size_t gi = (size_t)row * N + col;
                if (EPI == 0 || EPI == 1) {
                    if (EPI == 1) {
                        float2 rv = *(const float2*)(res + gi);
                        v0 += rv.x; v1 += rv.y;
                    }
                    *(float2*)(outf + gi) = make_float2(v0, v1);
                } else {
                    v0 = gelu_tanh(v0);
                    v1 = gelu_tanh(v1);
                    __nv_bfloat16 h0, l0, h1, l1;
                    split_bf16(v0, h0, l0);
                    split_bf16(v1, h1, l1);
                    *(__nv_bfloat162*)(oh + gi) = __nv_bfloat162{h0, h1};
                    *(__nv_bfloat162*)(ol + gi) = __nv_bfloat162{l0, l1};
                }
            }
        }
    }
}

// ---------------------------------------------------------------------------
// Flash attention (fp32, causal), HD=64, 64x64 tiles, 256 threads.
// Outputs y as bf16 hi/lo split for the proj GEMM.
// ---------------------------------------------------------------------------
#define VS_STRIDE 68
#define PS_STRIDE 65

__global__ __launch_bounds__(256) void flash_kernel(
    const float* __restrict__ qkv, __nv_bfloat16* __restrict__ yh,
    __nv_bfloat16* __restrict__ yl)
{
    extern __shared__ float sm[];
    float* Qs = sm;
    float* Ks = Qs + 64 * 64;
    float* Vs = Ks + 64 * 64;
    float* Ps = Vs + 64 * VS_STRIDE;
    float* alpha_s = Ps + 64 * PS_STRIDE;
    float* lsum_s  = alpha_s + 64;

    int tid = threadIdx.x;
    int bh = blockIdx.y;
    int bb = bh >> 4;
    int h  = bh & 15;
    int q0 = blockIdx.x * 64;
    const int C3 = 3 * C_DIM;
    const float scale = 0.125f;

    int rr = tid & 63;
    int dchunk = tid >> 6;

    const float* qbase = qkv + (size_t)(bb * T_SEQ + q0) * C3 + h * HDIM;
    #pragma unroll
    for (int it = 0; it < 4; it++) {
        int d0 = dchunk * 16 + it * 4;
        float4 v = *(const float4*)(qbase + (size_t)rr * C3 + d0);
        Qs[(d0 + 0) * 64 + rr] = v.x * scale;
        Qs[(d0 + 1) * 64 + rr] = v.y * scale;
        Qs[(d0 + 2) * 64 + rr] = v.z * scale;
        Qs[(d0 + 3) * 64 + rr] = v.w * scale;
    }

    int ty = tid >> 4, tx = tid & 15;
    int r_smax = tid >> 2;
    int csub   = tid & 3;

    float acc[4][4];
    #pragma unroll
    for (int i = 0; i < 4; i++)
        #pragma unroll
        for (int j = 0; j < 4; j++) acc[i][j] = 0.0f;

    float m_run = -1e30f;
    float l_run = 0.0f;

    for (int k0 = 0; k0 <= q0 + 63; k0 += 64) {
        __syncthreads();
        const float* kbase = qkv + (size_t)(bb * T_SEQ + k0) * C3 + C_DIM + h * HDIM;
        const float* vbase = kbase + C_DIM;
        #pragma unroll
        for (int it = 0; it < 4; it++) {
            int d0 = dchunk * 16 + it * 4;
            float4 kv = *(const float4*)(kbase + (size_t)rr * C3 + d0);
            Ks[(d0 + 0) * 64 + rr] = kv.x;
            Ks[(d0 + 1) * 64 + rr] = kv.y;
            Ks[(d0 + 2) * 64 + rr] = kv.z;
            Ks[(d0 + 3) * 64 + rr] = kv.w;
            float4 vv = *(const float4*)(vbase + (size_t)rr * C3 + d0);
            *(float4*)(Vs + rr * VS_STRIDE + d0) = vv;
        }
        __syncthreads();

        float s[4][4];
        #pragma unroll
        for (int i = 0; i < 4; i++)
            #pragma unroll
            for (int j = 0; j < 4; j++) s[i][j] = 0.0f;
        #pragma unroll 8
        for (int d = 0; d < 64; d++) {
            float4 qa = *(float4*)(Qs + d * 64 + ty * 4);
            float4 kb = *(float4*)(Ks + d * 64 + tx * 4);
            float aa[4] = {qa.x, qa.y, qa.z, qa.w};
            float bbv[4] = {kb.x, kb.y, kb.z, kb.w};
            #pragma unroll
            for (int i = 0; i < 4; i++)
                #pragma unroll
                for (int j = 0; j < 4; j++)
                    s[i][j] += aa[i] * bbv[j];
        }
        #pragma unroll
        for (int i = 0; i < 4; i++) {
            int gr = q0 + ty * 4 + i;
            #pragma unroll
            for (int j = 0; j < 4; j++) {
                int gc = k0 + tx * 4 + j;
                float val = (gc <= gr) ? s[i][j] : -1e30f;
                Ps[(tx * 4 + j) * PS_STRIDE + (ty * 4 + i)] = val;
            }
        }
        __syncthreads();

        float vals[16];
        float mt = -1e30f;
        #pragma unroll
        for (int k = 0; k < 16; k++) {
            vals[k] = Ps[(csub + 4 * k) * PS_STRIDE + r_smax];
            mt = fmaxf(mt, vals[k]);
        }
        mt = fmaxf(mt, __shfl_xor_sync(0xffffffffu, mt, 1));
        mt = fmaxf(mt, __shfl_xor_sync(0xffffffffu, mt, 2));
        float m_new = fmaxf(m_run, mt);
        float alpha = __expf(m_run - m_new);
        float sumloc = 0.0f;
        #pragma unroll
        for (int k = 0; k < 16; k++) {
            float p = __expf(vals[k] - m_new);
            Ps[(csub + 4 * k) * PS_STRIDE + r_smax] = p;
            sumloc += p;
        }
        sumloc += __shfl_xor_sync(0xffffffffu, sumloc, 1);
        sumloc += __shfl_xor_sync(0xffffffffu, sumloc, 2);
        l_run = l_run * alpha + sumloc;
        m_run = m_new;
        if (csub == 0) alpha_s[r_smax] = alpha;
        __syncthreads();

        #pragma unroll
        for (int i = 0; i < 4; i++) {
            float al = alpha_s[ty * 4 + i];
            #pragma unroll
            for (int j = 0; j < 4; j++) acc[i][j] *= al;
        }
        #pragma unroll 8
        for (int c = 0; c < 64; c++) {
            float p0 = Ps[c * PS_STRIDE + ty * 4 + 0];
            float p1 = Ps[c * PS_STRIDE + ty * 4 + 1];
            float p2 = Ps[c * PS_STRIDE + ty * 4 + 2];
            float p3 = Ps[c * PS_STRIDE + ty * 4 + 3];
            float4 vv = *(float4*)(Vs + c * VS_STRIDE + tx * 4);
            acc[0][0] += p0 * vv.x; acc[0][1] += p0 * vv.y; acc[0][2] += p0 * vv.z; acc[0][3] += p0 * vv.w;
            acc[1][0] += p1 * vv.x; acc[1][1] += p1 * vv.y; acc[1][2] += p1 * vv.z; acc[1][3] += p1 * vv.w;
            acc[2][0] += p2 * vv.x; acc[2][1] += p2 * vv.y; acc[2][2] += p2 * vv.z; acc[2][3] += p2 * vv.w;
            acc[3][0] += p3 * vv.x; acc[3][1] += p3 * vv.y; acc[3][2] += p3 * vv.z; acc[3][3] += p3 * vv.w;
        }
    }

    if (csub == 0) lsum_s[r_smax] = l_run;
    __syncthreads();

    #pragma unroll
    for (int i = 0; i < 4; i++) {
        float inv = 1.0f / lsum_s[ty * 4 + i];
        float o0 = acc[i][0] * inv, o1 = acc[i][1] * inv;
        float o2 = acc[i][2] * inv, o3 = acc[i][3] * inv;
        __nv_bfloat16 h0,h1,h2,h3,l0,l1,l2,l3;
        split_bf16(o0,h0,l0); split_bf16(o1,h1,l1);
        split_bf16(o2,h2,l2); split_bf16(o3,h3,l3);
        size_t row = (size_t)(bb * T_SEQ + q0 + ty * 4 + i);
        size_t base = row * C_DIM + h * HDIM + tx * 4;
        ((__nv_bfloat162*)(yh + base))[0] = __nv_bfloat162{h0, h1};
        ((__nv_bfloat162*)(yh + base))[1] = __nv_bfloat162{h2, h3};
        ((__nv_bfloat162*)(yl + base))[0] = __nv_bfloat162{l0, l1};
        ((__nv_bfloat162*)(yl + base))[1] = __nv_bfloat162{l2, l3};
    }
}

// ---------------------------------------------------------------------------
// Launch
// ---------------------------------------------------------------------------
extern "C" void kernel_launch(void* const* d_in, const int* in_sizes, int n_in,
                              void* d_out, int out_size)
{
    const float* x      = (const float*)d_in[0];
    const float* ln1_g  = (const float*)d_in[1];
    const float* ln1_b  = (const float*)d_in[2];
    const float* W_attn = (const float*)d_in[3];
    const float* b_attn = (const float*)d_in[4];
    const float* W_proj = (const float*)d_in[5];
    const float* b_proj = (const float*)d_in[6];
    const float* ln2_g  = (const float*)d_in[7];
    const float* ln2_b  = (const float*)d_in[8];
    const float* W_fc   = (const float*)d_in[9];
    const float* b_fc   = (const float*)d_in[10];
    const float* W_fc2  = (const float*)d_in[11];
    const float* b_fc2  = (const float*)d_in[12];
    float* out = (float*)d_out;

    float *p_qkv, *p_x2;
    __nv_bfloat16 *p_ah, *p_al, *p_yh, *p_yl, *p_mh, *p_ml;
    __nv_bfloat16 *p_wah, *p_wal, *p_wph, *p_wpl, *p_wfh, *p_wfl, *p_w2h, *p_w2l;
    cudaGetSymbolAddress((void**)&p_qkv, g_qkv_buf);
    cudaGetSymbolAddress((void**)&p_x2,  g_x2_buf);
    cudaGetSymbolAddress((void**)&p_ah,  g_ah);
    cudaGetSymbolAddress((void**)&p_al,  g_al);
    cudaGetSymbolAddress((void**)&p_yh,  g_yh);
    cudaGetSymbolAddress((void**)&p_yl,  g_yl);
    cudaGetSymbolAddress((void**)&p_mh,  g_mh);
    cudaGetSymbolAddress((void**)&p_ml,  g_ml);
    cudaGetSymbolAddress((void**)&p_wah, g_wattn_h);
    cudaGetSymbolAddress((void**)&p_wal, g_wattn_l);
    cudaGetSymbolAddress((void**)&p_wph, g_wproj_h);
    cudaGetSymbolAddress((void**)&p_wpl, g_wproj_l);
    cudaGetSymbolAddress((void**)&p_wfh, g_wfc_h);
    cudaGetSymbolAddress((void**)&p_wfl, g_wfc_l);
    cudaGetSymbolAddress((void**)&p_w2h, g_wfc2_h);
    cudaGetSymbolAddress((void**)&p_w2l, g_wfc2_l);

    size_t fa_smem = (size_t)(64*64 + 64*64 + 64*VS_STRIDE + 64*PS_STRIDE + 128) * sizeof(float);
    cudaFuncSetAttribute(flash_kernel, cudaFuncAttributeMaxDynamicSharedMemorySize, (int)fa_smem);
    cudaFuncSetAttribute(hmma_gemm<0>, cudaFuncAttributeMaxDynamicSharedMemorySize, GEMM_SMEM);
    cudaFuncSetAttribute(hmma_gemm<1>, cudaFuncAttributeMaxDynamicSharedMemorySize, GEMM_SMEM);
    cudaFuncSetAttribute(hmma_gemm<2>, cudaFuncAttributeMaxDynamicSharedMemorySize, GEMM_SMEM);

    dim3 tb(32, 8);
    // Weight prep (transpose + split)
    transpose_split_kernel<<<dim3(3 * C_DIM / 32, C_DIM / 32), tb>>>(W_attn, p_wah, p_wal, C_DIM, 3 * C_DIM);
    transpose_split_kernel<<<dim3(C_DIM / 32, C_DIM / 32), tb>>>(W_proj, p_wph, p_wpl, C_DIM, C_DIM);
    transpose_split_kernel<<<dim3(4 * C_DIM / 32, C_DIM / 32), tb>>>(W_fc, p_wfh, p_wfl, C_DIM, 4 * C_DIM);
    transpose_split_kernel<<<dim3(C_DIM / 32, 4 * C_DIM / 32), tb>>>(W_fc2, p_w2h, p_w2l, 4 * C_DIM, C_DIM);

    // 1. LN1 -> split
    ln_kernel<<<N_TOK, 256>>>(x, ln1_g, ln1_b, p_ah, p_al);
    // 2. QKV GEMM (fp32 out)
    hmma_gemm<0><<<dim3(3 * C_DIM / 128, N_TOK / 128), 256, GEMM_SMEM>>>(
        p_ah, p_al, p_wah, p_wal, b_attn, nullptr, p_qkv, nullptr, nullptr,
        N_TOK, 3 * C_DIM, C_DIM);
    // 3. Flash attention -> split y
    flash_kernel<<<dim3(T_SEQ / 64, B_SZ * NH), 256, fa_smem>>>(p_qkv, p_yh, p_yl);
    // 4. Proj GEMM + residual (fp32 out)
    hmma_gemm<1><<<dim3(C_DIM / 128, N_TOK / 128), 256, GEMM_SMEM>>>(
        p_yh, p_yl, p_wph, p_wpl, b_proj, x, p_x2, nullptr, nullptr,
        N_TOK, C_DIM, C_DIM);
    // 5. LN2 -> split
    ln_kernel<<<N_TOK, 256>>>(p_x2, ln2_g, ln2_b, p_ah, p_al);
    // 6. FC GEMM + GELU -> split act
    hmma_gemm<2><<<dim3(4 * C_DIM / 128, N_TOK / 128), 256, GEMM_SMEM>>>(
        p_ah, p_al, p_wfh, p_wfl, b_fc, nullptr, nullptr, p_mh, p_ml,
        N_TOK, 4 * C_DIM, C_DIM);
    // 7. FC2 GEMM + residual -> final out
    hmma_gemm<1><<<dim3(C_DIM / 128, N_TOK / 128), 256, GEMM_SMEM>>>(
        p_mh, p_ml, p_w2h, p_w2l, b_fc2, p_x2, out, nullptr, nullptr,
        N_TOK, C_DIM, 4 * C_DIM);
}

// round 4
// speedup vs baseline: 2.4177x; 1.3964x over previous
#include <cuda_runtime.h>
#include <cuda_bf16.h>
#include <math.h>
#include <stdint.h>

// Problem constants
#define B_SZ   2
#define T_SEQ  2048
#define C_DIM  1024
#define NH     16
#define HDIM   64
#define N_TOK  (B_SZ * T_SEQ)   // 4096

// ---------------------------------------------------------------------------
// Scratch (device globals; runtime alloc is forbidden)
// ---------------------------------------------------------------------------
__device__ float         g_x2_buf [N_TOK * C_DIM];         // x after attn residual
__device__ __nv_bfloat16 g_ah[N_TOK * C_DIM];              // LN out hi
__device__ __nv_bfloat16 g_al[N_TOK * C_DIM];              // LN out lo
__device__ __nv_bfloat16 g_yh[N_TOK * C_DIM];              // attn out hi
__device__ __nv_bfloat16 g_yl[N_TOK * C_DIM];              // attn out lo
__device__ __nv_bfloat16 g_mh[N_TOK * 4 * C_DIM];          // gelu act hi
__device__ __nv_bfloat16 g_ml[N_TOK * 4 * C_DIM];          // gelu act lo
// Q/K/V head-major planes [(b*NH+h)][t][64], hi/lo. Q pre-scaled by 1/8.
__device__ __nv_bfloat16 g_q_h[N_TOK * C_DIM], g_q_l[N_TOK * C_DIM];
__device__ __nv_bfloat16 g_k_h[N_TOK * C_DIM], g_k_l[N_TOK * C_DIM];
__device__ __nv_bfloat16 g_v_h[N_TOK * C_DIM], g_v_l[N_TOK * C_DIM];
// Transposed + split weights: Wt[n*K + k] = W[k*N + n]
__device__ __nv_bfloat16 g_wattn_h[3 * C_DIM * C_DIM], g_wattn_l[3 * C_DIM * C_DIM];
__device__ __nv_bfloat16 g_wproj_h[C_DIM * C_DIM],     g_wproj_l[C_DIM * C_DIM];
__device__ __nv_bfloat16 g_wfc_h  [4 * C_DIM * C_DIM], g_wfc_l  [4 * C_DIM * C_DIM];
__device__ __nv_bfloat16 g_wfc2_h [C_DIM * 4 * C_DIM], g_wfc2_l [C_DIM * 4 * C_DIM];

// ---------------------------------------------------------------------------
// Helpers
// ---------------------------------------------------------------------------
__device__ __forceinline__ float gelu_tanh(float v) {
    float v3 = v * v * v;
    return 0.5f * v * (1.0f + tanhf(0.7978845608028654f * (v + 0.044715f * v3)));
}

__device__ __forceinline__ void split_bf16(float v, __nv_bfloat16& h, __nv_bfloat16& l) {
    h = __float2bfloat16(v);
    l = __float2bfloat16(v - __bfloat162float(h));
}

// Fast exp on the FMA pipe (no MUFU). Valid for x <= 0 (softmax args).
__device__ __forceinline__ float fexp(float x) {
    float t = fmaxf(x * 1.4426950408889634f, -126.0f);
    float fi = t + 12582912.0f;                       // round-to-nearest int
    int   ii = __float_as_int(fi) - 0x4B400000;       // = rint(t)
    float f  = t - (fi - 12582912.0f);                // frac in [-0.5, 0.5]
    float p  = 1.3333558146e-3f;
    p = fmaf(p, f, 9.6181291056e-3f);
    p = fmaf(p, f, 5.5504108664e-2f);
    p = fmaf(p, f, 2.4022650696e-1f);
    p = fmaf(p, f, 6.9314718056e-1f);
    p = fmaf(p, f, 1.0f);
    return __int_as_float((ii + 127) << 23) * p;
}

__device__ __forceinline__ uint32_t smem_u32(const void* p) {
    uint32_t a;
    asm("{ .reg .u64 t; cvta.to.shared.u64 t, %1; cvt.u32.u64 %0, t; }" : "=r"(a) : "l"(p));
    return a;
}

__device__ __forceinline__ void ldm_x4(uint32_t* r, uint32_t addr) {
    asm volatile("ldmatrix.sync.aligned.m8n8.x4.shared.b16 {%0,%1,%2,%3}, [%4];"
                 : "=r"(r[0]), "=r"(r[1]), "=r"(r[2]), "=r"(r[3]) : "r"(addr));
}

__device__ __forceinline__ void ldm_x4t(uint32_t* r, uint32_t addr) {
    asm volatile("ldmatrix.sync.aligned.m8n8.x4.trans.shared.b16 {%0,%1,%2,%3}, [%4];"
                 : "=r"(r[0]), "=r"(r[1]), "=r"(r[2]), "=r"(r[3]) : "r"(addr));
}

__device__ __forceinline__ void mma_bf16(float* c, const uint32_t* a, const uint32_t* b) {
    asm volatile(
        "mma.sync.aligned.m16n8k16.row.col.f32.bf16.bf16.f32 "
        "{%0,%1,%2,%3}, {%4,%5,%6,%7}, {%8,%9}, {%0,%1,%2,%3};"
        : "+f"(c[0]), "+f"(c[1]), "+f"(c[2]), "+f"(c[3])
        : "r"(a[0]), "r"(a[1]), "r"(a[2]), "r"(a[3]), "r"(b[0]), "r"(b[1]));
}

__device__ __forceinline__ void cp16(uint32_t saddr, const void* g) {
    asm volatile("cp.async.cg.shared.global [%0], [%1], 16;" :: "r"(saddr), "l"(g));
}
#define CP_COMMIT() asm volatile("cp.async.commit_group;")
#define CP_WAIT(n)  asm volatile("cp.async.wait_group %0;" :: "n"(n))

__device__ __forceinline__ uint32_t pack_bf2(__nv_bfloat16 a, __nv_bfloat16 b) {
    __nv_bfloat162 t{a, b};
    return *reinterpret_cast<uint32_t*>(&t);
}

// GEMM smem tile geometry: 128 rows x 32 bf16, row stride 40 elems (80 B)
#define T_STRIDE   40
#define T_ROWB     80
#define T_BYTES    10240
#define BUF_BYTES  (4 * T_BYTES)
#define GEMM_SMEM  (2 * BUF_BYTES)       // 81920

// ---------------------------------------------------------------------------
// Weight transpose + hi/lo split
// ---------------------------------------------------------------------------
__global__ __launch_bounds__(256) void transpose_split_kernel(
    const float* __restrict__ W, __nv_bfloat16* __restrict__ Th,
    __nv_bfloat16* __restrict__ Tl, int K, int N)
{
    __shared__ float t[32][33];
    int n0 = blockIdx.x * 32, k0 = blockIdx.y * 32;
    int tx = threadIdx.x, ty = threadIdx.y;
    #pragma unroll
    for (int i = 0; i < 4; i++)
        t[ty + 8 * i][tx] = W[(size_t)(k0 + ty + 8 * i) * N + n0 + tx];
    __syncthreads();
    #pragma unroll
    for (int i = 0; i < 4; i++) {
        float v = t[tx][ty + 8 * i];
        __nv_bfloat16 h, l;
        split_bf16(v, h, l);
        size_t o = (size_t)(n0 + ty + 8 * i) * K + k0 + tx;
        Th[o] = h;
        Tl[o] = l;
    }
}

// ---------------------------------------------------------------------------
// LayerNorm -> bf16 hi/lo split output
// ---------------------------------------------------------------------------
__global__ __launch_bounds__(256) void ln_kernel(
    const float* __restrict__ x, const float* __restrict__ g,
    const float* __restrict__ b, __nv_bfloat16* __restrict__ oh,
    __nv_bfloat16* __restrict__ ol)
{
    __shared__ float red[8];
    int row = blockIdx.x;
    int tid = threadIdx.x;
    const float4* x4 = (const float4*)(x + (size_t)row * C_DIM);
    float4 v = x4[tid];

    float s = v.x + v.y + v.z + v.w;
    #pragma unroll
    for (int o = 16; o; o >>= 1) s += __shfl_xor_sync(0xffffffffu, s, o);
    if ((tid & 31) == 0) red[tid >> 5] = s;
    __syncthreads();
    s = red[0] + red[1] + red[2] + red[3] + red[4] + red[5] + red[6] + red[7];
    float mu = s * (1.0f / C_DIM);

    float dx0 = v.x - mu, dx1 = v.y - mu, dx2 = v.z - mu, dx3 = v.w - mu;
    float q = dx0*dx0 + dx1*dx1 + dx2*dx2 + dx3*dx3;
    #pragma unroll
    for (int o = 16; o; o >>= 1) q += __shfl_xor_sync(0xffffffffu, q, o);
    __syncthreads();
    if ((tid & 31) == 0) red[tid >> 5] = q;
    __syncthreads();
    q = red[0] + red[1] + red[2] + red[3] + red[4] + red[5] + red[6] + red[7];
    float rs = rsqrtf(q * (1.0f / C_DIM) + 1e-5f);

    float4 gg = ((const float4*)g)[tid];
    float4 bb = ((const float4*)b)[tid];
    float o0 = dx0 * rs * gg.x + bb.x;
    float o1 = dx1 * rs * gg.y + bb.y;
    float o2 = dx2 * rs * gg.z + bb.z;
    float o3 = dx3 * rs * gg.w + bb.w;

    __nv_bfloat16 h0,h1,h2,h3,l0,l1,l2,l3;
    split_bf16(o0,h0,l0); split_bf16(o1,h1,l1);
    split_bf16(o2,h2,l2); split_bf16(o3,h3,l3);
    size_t base = (size_t)row * C_DIM + tid * 4;
    ((__nv_bfloat162*)(oh + base))[0] = __nv_bfloat162{h0, h1};
    ((__nv_bfloat162*)(oh + base))[1] = __nv_bfloat162{h2, h3};
    ((__nv_bfloat162*)(ol + base))[0] = __nv_bfloat162{l0, l1};
    ((__nv_bfloat162*)(ol + base))[1] = __nv_bfloat162{l2, l3};
}

// ---------------------------------------------------------------------------
// HMMA GEMM: D[M,N] = A[M,K] @ B[N,K]^T via 3-pass bf16 split (mma.sync).
// EPI: 0 fp32+bias; 1 fp32+bias+res; 2 gelu->bf16 split; 3 qkv->head-major split
// ---------------------------------------------------------------------------
template<int EPI>
__global__ __launch_bounds__(256) void hmma_gemm(
    const __nv_bfloat16* __restrict__ Ahi, const __nv_bfloat16* __restrict__ Alo,
    const __nv_bfloat16* __restrict__ Bhi, const __nv_bfloat16* __restrict__ Blo,
    const float* __restrict__ bias, const float* __restrict__ res,
    float* __restrict__ outf, __nv_bfloat16* __restrict__ oh,
    __nv_bfloat16* __restrict__ ol,
    __nv_bfloat16* __restrict__ q_h, __nv_bfloat16* __restrict__ q_l,
    __nv_bfloat16* __restrict__ k_h, __nv_bfloat16* __restrict__ k_l,
    __nv_bfloat16* __restrict__ v_h, __nv_bfloat16* __restrict__ v_l,
    int M, int N, int K)
{
    extern __shared__ char smem[];
    uint32_t sb = smem_u32(smem);
    int tid = threadIdx.x, lane = tid & 31, w = tid >> 5;
    int wm = w >> 2, wn = w & 3;
    int m0 = blockIdx.y * 128, n0 = blockIdx.x * 128;

    const __nv_bfloat16* srcs[4] = {
        Ahi + (size_t)m0 * K, Alo + (size_t)m0 * K,
        Bhi + (size_t)n0 * K, Blo + (size_t)n0 * K };

    float acc[4][4][4];
    #pragma unroll
    for (int a = 0; a < 4; a++)
        #pragma unroll
        for (int b = 0; b < 4; b++)
            #pragma unroll
            for (int c = 0; c < 4; c++) acc[a][b][c] = 0.0f;

    const int nch = K >> 5;

    #pragma unroll
    for (int t = 0; t < 4; t++) {
        #pragma unroll
        for (int u = 0; u < 2; u++) {
            int idx = tid + 256 * u;
            int r = idx >> 2, c = idx & 3;
            cp16(sb + t * T_BYTES + r * T_ROWB + c * 16, srcs[t] + (size_t)r * K + c * 8);
        }
    }
    CP_COMMIT();

    for (int ch = 0; ch < nch; ch++) {
        uint32_t buf = sb + (ch & 1) * BUF_BYTES;
        if (ch + 1 < nch) {
            uint32_t nbuf = sb + ((ch + 1) & 1) * BUF_BYTES;
            int k0 = (ch + 1) << 5;
            #pragma unroll
            for (int t = 0; t < 4; t++) {
                #pragma unroll
                for (int u = 0; u < 2; u++) {
                    int idx = tid + 256 * u;
                    int r = idx >> 2, c = idx & 3;
                    cp16(nbuf + t * T_BYTES + r * T_ROWB + c * 16,
                         srcs[t] + (size_t)r * K + k0 + c * 8);
                }
            }
            CP_COMMIT();
            CP_WAIT(1);
        } else {
            CP_WAIT(0);
        }
        __syncthreads();

        uint32_t abase = buf;
        uint32_t bbase = buf + 2 * T_BYTES;

        int arow = (lane & 7) + ((lane >> 3) & 1) * 8;
        int akof = ((lane >> 4) & 1) * 8;
        int brow = (lane & 7) + ((lane >> 4) & 1) * 8;
        int bkof = ((lane >> 3) & 1) * 8;

        #pragma unroll
        for (int ks = 0; ks < 2; ks++) {
            uint32_t Ah[4][4], Al[4][4], Bh[4][2], Bl[4][2];
            #pragma unroll
            for (int mf = 0; mf < 4; mf++) {
                uint32_t ad = abase + (uint32_t)(((wm * 64 + mf * 16 + arow) * T_STRIDE
                                                 + ks * 16 + akof) * 2);
                ldm_x4(Ah[mf], ad);
                ldm_x4(Al[mf], ad + T_BYTES);
            }
            #pragma unroll
            for (int np = 0; np < 2; np++) {
                uint32_t bd = bbase + (uint32_t)(((wn * 32 + np * 16 + brow) * T_STRIDE
                                                 + ks * 16 + bkof) * 2);
                uint32_t th[4], tl[4];
                ldm_x4(th, bd);
                ldm_x4(tl, bd + T_BYTES);
                Bh[np*2][0]=th[0]; Bh[np*2][1]=th[1]; Bh[np*2+1][0]=th[2]; Bh[np*2+1][1]=th[3];
                Bl[np*2][0]=tl[0]; Bl[np*2][1]=tl[1]; Bl[np*2+1][0]=tl[2]; Bl[np*2+1][1]=tl[3];
            }
            #pragma unroll
            for (int mf = 0; mf < 4; mf++)
                #pragma unroll
                for (int nf = 0; nf < 4; nf++)
                    mma_bf16(acc[mf][nf], Ah[mf], Bh[nf]);
            #pragma unroll
            for (int mf = 0; mf < 4; mf++)
                #pragma unroll
                for (int nf = 0; nf < 4; nf++)
                    mma_bf16(acc[mf][nf], Ah[mf], Bl[nf]);
            #pragma unroll
            for (int mf = 0; mf < 4; mf++)
                #pragma unroll
                for (int nf = 0; nf < 4; nf++)
                    mma_bf16(acc[mf][nf], Al[mf], Bh[nf]);
        }
        __syncthreads();
    }

    int qr = lane >> 2;
    int qc = (lane & 3) * 2;
    #pragma unroll
    for (int mf = 0; mf < 4; mf++) {
        #pragma unroll
        for (int nf = 0; nf < 4; nf++) {
            int col = n0 + wn * 32 + nf * 8 + qc;
            float b0 = bias[col], b1 = bias[col + 1];
            #pragma unroll
            for (int half = 0; half < 2; half++) {
                int row = m0 + wm * 64 + mf * 16 + qr + half * 8;
                float v0 = acc[mf][nf][half * 2 + 0] + b0;
                float v1 = acc[mf][nf][half * 2 + 1] + b1;
                if (EPI == 0 || EPI == 1) {
                    size_t gi = (size_t)row * N + col;
                    if (EPI == 1) {
                        float2 rv = *(const float2*)(res + gi);
                        v0 += rv.x; v1 += rv.y;
                    }
                    *(float2*)(outf + gi) = make_float2(v0, v1);
                } else if (EPI == 2) {
                    size_t gi = (size_t)row * N + col;
                    v0 = gelu_tanh(v0);
                    v1 = gelu_tanh(v1);
                    __nv_bfloat16 h0, l0, h1, l1;
                    split_bf16(v0, h0, l0);
                    split_bf16(v1, h1, l1);
                    *(__nv_bfloat162*)(oh + gi) = __nv_bfloat162{h0, h1};
                    *(__nv_bfloat162*)(ol + gi) = __nv_bfloat162{l0, l1};
                } else {
                    // QKV: section 0=q (scale 1/8), 1=k, 2=v; head-major planes
                    int sec = col >> 10;
                    int within = col & 1023;
                    int hd = within >> 6, d = within & 63;
                    if (sec == 0) { v0 *= 0.125f; v1 *= 0.125f; }
                    __nv_bfloat16 h0, l0, h1, l1;
                    split_bf16(v0, h0, l0);
                    split_bf16(v1, h1, l1);
                    size_t gi = ((size_t)((row >> 11) * NH + hd) * T_SEQ + (row & 2047)) * 64 + d;
                    __nv_bfloat16* dh = (sec == 0) ? q_h : (sec == 1) ? k_h : v_h;
                    __nv_bfloat16* dl = (sec == 0) ? q_l : (sec == 1) ? k_l : v_l;
                    *(__nv_bfloat162*)(dh + gi) = __nv_bfloat162{h0, h1};
                    *(__nv_bfloat162*)(dl + gi) = __nv_bfloat162{l0, l1};
                }
            }
        }
    }
}

// ---------------------------------------------------------------------------
// Flash attention, HMMA bf16 3-pass, causal, HD=64.
// q-tile 128 (8 warps x m16), kv-tile 64, cp.async double-buffered K/V.
// ---------------------------------------------------------------------------
#define FQT   144                      // smem row pitch bytes (64 bf16 + pad)
#define FQSZ  (128 * FQT * 2)          // Q hi+lo = 36864
#define FTSZ  (64 * FQT)               // one 64-row tile = 9216
#define FKVSZ (4 * FTSZ)               // Khi,Klo,Vhi,Vlo = 36864
#define FLASH_SMEM (FQSZ + 2 * FKVSZ)  // 110592

__global__ __launch_bounds__(256) void flash_hmma(
    const __nv_bfloat16* __restrict__ qh, const __nv_bfloat16* __restrict__ ql,
    const __nv_bfloat16* __restrict__ kh, const __nv_bfloat16* __restrict__ kl,
    const __nv_bfloat16* __restrict__ vh, const __nv_bfloat16* __restrict__ vl,
    __nv_bfloat16* __restrict__ yh, __nv_bfloat16* __restrict__ yl)
{
    extern __shared__ char smf[];
    uint32_t sb = smem_u32(smf);
    int tid = threadIdx.x, lane = tid & 31, w = tid >> 5;
    int bh = blockIdx.y;
    int qb = blockIdx.x * 128;
    size_t plane = (size_t)bh * (T_SEQ * 64);

    const __nv_bfloat16* qs[2] = { qh + plane + (size_t)qb * 64, ql + plane + (size_t)qb * 64 };
    const __nv_bfloat16* ks[4] = { kh + plane, kl + plane, vh + plane, vl + plane };

    // Q tiles (hi/lo) via cp.async
    #pragma unroll
    for (int u = 0; u < 8; u++) {
        int idx = tid + 256 * u;
        int t = idx >> 10, r = (idx >> 3) & 127, c = idx & 7;
        cp16(sb + t * (128 * FQT) + r * FQT + c * 16, qs[t] + (size_t)r * 64 + c * 8);
    }
    CP_COMMIT();
    // KV tile 0 -> buffer 0
    #pragma unroll
    for (int u = 0; u < 8; u++) {
        int idx = tid + 256 * u;
        int t = idx >> 9, r = (idx >> 3) & 63, c = idx & 7;
        cp16(sb + FQSZ + t * FTSZ + r * FQT + c * 16, ks[t] + (size_t)r * 64 + c * 8);
    }
    CP_COMMIT();
    CP_WAIT(1);
    __syncthreads();

    // Q fragments (held in registers for the whole kernel)
    int arow = (lane & 7) + ((lane >> 3) & 1) * 8;
    int akof = ((lane >> 4) & 1) * 8;
    uint32_t QHf[4][4], QLf[4][4];
    #pragma unroll
    for (int kc = 0; kc < 4; kc++) {
        uint32_t ad = sb + (uint32_t)((w * 16 + arow) * FQT + (kc * 16 + akof) * 2);
        ldm_x4(QHf[kc], ad);
        ldm_x4(QLf[kc], ad + 128 * FQT);
    }

    float oacc[8][4];
    #pragma unroll
    for (int j = 0; j < 8; j++)
        #pragma unroll
        for (int c = 0; c < 4; c++) oacc[j][c] = 0.0f;
    float m_run[2] = { -1e30f, -1e30f };
    float l_run[2] = { 0.0f, 0.0f };

    int brow = (lane & 7) + ((lane >> 4) & 1) * 8;   // S: B=K tile rows (kv)
    int bkof = ((lane >> 3) & 1) * 8;                // S: d offset
    int vrow = (lane & 7) + ((lane >> 3) & 1) * 8;   // PV: V rows (kv = k-dim)
    int vcol = ((lane >> 4) & 1) * 8;                // PV: d offset (n-dim)

    const int nkv = (qb >> 6) + 2;
    for (int it = 0; it < nkv; it++) {
        if (it + 1 < nkv) {
            int kb2 = (it + 1) << 6;
            uint32_t nb_ = sb + FQSZ + ((it + 1) & 1) * FKVSZ;
            #pragma unroll
            for (int u = 0; u < 8; u++) {
                int idx = tid + 256 * u;
                int t = idx >> 9, r = (idx >> 3) & 63, c = idx & 7;
                cp16(nb_ + t * FTSZ + r * FQT + c * 16, ks[t] + (size_t)(kb2 + r) * 64 + c * 8);
            }
            CP_COMMIT();
            CP_WAIT(1);
        } else {
            CP_WAIT(0);
        }
        __syncthreads();
        uint32_t kvb = sb + FQSZ + (it & 1) * FKVSZ;

        // ---- S = Q K^T (3-pass) ----
        float sacc[8][4];
        #pragma unroll
        for (int j = 0; j < 8; j++)
            #pragma unroll
            for (int c = 0; c < 4; c++) sacc[j][c] = 0.0f;

        #pragma unroll
        for (int kc = 0; kc < 4; kc++) {
            #pragma unroll
            for (int nb2 = 0; nb2 < 4; nb2++) {
                uint32_t ad = kvb + (uint32_t)((nb2 * 16 + brow) * FQT + (kc * 16 + bkof) * 2);
                uint32_t th[4], tl[4];
                ldm_x4(th, ad);
                ldm_x4(tl, ad + FTSZ);
                uint32_t bh0[2] = { th[0], th[1] }, bh1[2] = { th[2], th[3] };
                uint32_t bl0[2] = { tl[0], tl[1] }, bl1[2] = { tl[2], tl[3] };
                mma_bf16(sacc[nb2*2],   QHf[kc], bh0);
                mma_bf16(sacc[nb2*2+1], QHf[kc], bh1);
                mma_bf16(sacc[nb2*2],   QHf[kc], bl0);
                mma_bf16(sacc[nb2*2+1], QHf[kc], bl1);
                mma_bf16(sacc[nb2*2],   QLf[kc], bh0);
                mma_bf16(sacc[nb2*2+1], QLf[kc], bh1);
            }
        }

        // ---- causal mask ----
        int kb = it << 6;
        int qrow = qb + w * 16 + (lane >> 2);
        if (kb + 63 > qb + w * 16) {
            #pragma unroll
            for (int j = 0; j < 8; j++) {
                int col = kb + j * 8 + (lane & 3) * 2;
                #pragma unroll
                for (int rh = 0; rh < 2; rh++) {
                    int row = qrow + rh * 8;
                    if (col     > row) sacc[j][rh*2]   = -1e30f;
                    if (col + 1 > row) sacc[j][rh*2+1] = -1e30f;
                }
            }
        }

        // ---- online softmax (per row-half; 4 lanes share a row) ----
        #pragma unroll
        for (int rh = 0; rh < 2; rh++) {
            float mt = -1e30f;
            #pragma unroll
            for (int j = 0; j < 8; j++) {
                mt = fmaxf(mt, sacc[j][rh*2]);
                mt = fmaxf(mt, sacc[j][rh*2+1]);
            }
            mt = fmaxf(mt, __shfl_xor_sync(0xffffffffu, mt, 1));
            mt = fmaxf(mt, __shfl_xor_sync(0xffffffffu, mt, 2));
            float m_new = fmaxf(m_run[rh], mt);
            float alpha = fexp(m_run[rh] - m_new);
            m_run[rh] = m_new;
            float sum = 0.0f;
            #pragma unroll
            for (int j = 0; j < 8; j++) {
                float p0 = fexp(sacc[j][rh*2]   - m_new);
                float p1 = fexp(sacc[j][rh*2+1] - m_new);
                sacc[j][rh*2]   = p0;
                sacc[j][rh*2+1] = p1;
                sum += p0 + p1;
            }
            sum += __shfl_xor_sync(0xffffffffu, sum, 1);
            sum += __shfl_xor_sync(0xffffffffu, sum, 2);
            l_run[rh] = l_run[rh] * alpha + sum;
            #pragma unroll
            for (int j = 0; j < 8; j++) {
                oacc[j][rh*2]   *= alpha;
                oacc[j][rh*2+1] *= alpha;
            }
        }

        // ---- pack P into A fragments (hi/lo), straight from registers ----
        uint32_t PH[4][4], PL[4][4];
        #pragma unroll
        for (int kc = 0; kc < 4; kc++) {
            #pragma unroll
            for (int q4 = 0; q4 < 4; q4++) {
                int j  = kc * 2 + (q4 >> 1);
                int rh = q4 & 1;
                float p0 = sacc[j][rh*2], p1 = sacc[j][rh*2+1];
                __nv_bfloat16 h0, l0, h1, l1;
                split_bf16(p0, h0, l0);
                split_bf16(p1, h1, l1);
                PH[kc][q4] = pack_bf2(h0, h1);
                PL[kc][q4] = pack_bf2(l0, l1);
            }
        }

        // ---- O += P V (3-pass); V via ldmatrix.trans on [kv][d] tiles ----
        #pragma unroll
        for (int kc = 0; kc < 4; kc++) {
            #pragma unroll
            for (int nb2 = 0; nb2 < 4; nb2++) {
                uint32_t ad = kvb + 2 * FTSZ
                            + (uint32_t)((kc * 16 + vrow) * FQT + (nb2 * 16 + vcol) * 2);
                uint32_t th[4], tl[4];
                ldm_x4t(th, ad);
                ldm_x4t(tl, ad + FTSZ);
                uint32_t bh0[2] = { th[0], th[1] }, bh1[2] = { th[2], th[3] };
                uint32_t bl0[2] = { tl[0], tl[1] }, bl1[2] = { tl[2], tl[3] };
                mma_bf16(oacc[nb2*2],   PH[kc], bh0);
                mma_bf16(oacc[nb2*2+1], PH[kc], bh1);
                mma_bf16(oacc[nb2*2],   PH[kc], bl0);
                mma_bf16(oacc[nb2*2+1], PH[kc], bl1);
                mma_bf16(oacc[nb2*2],   PL[kc], bh0);
                mma_bf16(oacc[nb2*2+1], PL[kc], bh1);
            }
        }
        __syncthreads();
    }

    // ---- epilogue: O/l -> yh/yl [token][h*64+d] ----
    float inv0 = 1.0f / l_run[0];
    float inv1 = 1.0f / l_run[1];
    int b = bh >> 4, h = bh & 15;
    #pragma unroll
    for (int j = 0; j < 8; j++) {
        #pragma unroll
        for (int rh = 0; rh < 2; rh++) {
            float iv = rh ? inv1 : inv0;
            float o0 = oacc[j][rh*2]   * iv;
            float o1 = oacc[j][rh*2+1] * iv;
            __nv_bfloat16 h0, l0, h1, l1;
            split_bf16(o0, h0, l0);
            split_bf16(o1, h1, l1);
            size_t row = (size_t)b * T_SEQ + qb + w * 16 + (lane >> 2) + rh * 8;
            size_t gi = row * C_DIM + h * 64 + j * 8 + (lane & 3) * 2;
            *(__nv_bfloat162*)(yh + gi) = __nv_bfloat162{h0, h1};
            *(__nv_bfloat162*)(yl + gi) = __nv_bfloat162{l0, l1};
        }
    }
}

// ---------------------------------------------------------------------------
// Launch
// ---------------------------------------------------------------------------
extern "C" void kernel_launch(void* const* d_in, const int* in_sizes, int n_in,
                              void* d_out, int out_size)
{
    const float* x      = (const float*)d_in[0];
    const float* ln1_g  = (const float*)d_in[1];
    const float* ln1_b  = (const float*)d_in[2];
    const float* W_attn = (const float*)d_in[3];
    const float* b_attn = (const float*)d_in[4];
    const float* W_proj = (const float*)d_in[5];
    const float* b_proj = (const float*)d_in[6];
    const float* ln2_g  = (const float*)d_in[7];
    const float* ln2_b  = (const float*)d_in[8];
    const float* W_fc   = (const float*)d_in[9];
    const float* b_fc   = (const float*)d_in[10];
    const float* W_fc2  = (const float*)d_in[11];
    const float* b_fc2  = (const float*)d_in[12];
    float* out = (float*)d_out;

    float *p_x2;
    __nv_bfloat16 *p_ah, *p_al, *p_yh, *p_yl, *p_mh, *p_ml;
    __nv_bfloat16 *p_qh, *p_ql, *p_kh, *p_kl, *p_vh, *p_vl;
    __nv_bfloat16 *p_wah, *p_wal, *p_wph, *p_wpl, *p_wfh, *p_wfl, *p_w2h, *p_w2l;
    cudaGetSymbolAddress((void**)&p_x2,  g_x2_buf);
    cudaGetSymbolAddress((void**)&p_ah,  g_ah);
    cudaGetSymbolAddress((void**)&p_al,  g_al);
    cudaGetSymbolAddress((void**)&p_yh,  g_yh);
    cudaGetSymbolAddress((void**)&p_yl,  g_yl);
    cudaGetSymbolAddress((void**)&p_mh,  g_mh);
    cudaGetSymbolAddress((void**)&p_ml,  g_ml);
    cudaGetSymbolAddress((void**)&p_qh,  g_q_h);
    cudaGetSymbolAddress((void**)&p_ql,  g_q_l);
    cudaGetSymbolAddress((void**)&p_kh,  g_k_h);
    cudaGetSymbolAddress((void**)&p_kl,  g_k_l);
    cudaGetSymbolAddress((void**)&p_vh,  g_v_h);
    cudaGetSymbolAddress((void**)&p_vl,  g_v_l);
    cudaGetSymbolAddress((void**)&p_wah, g_wattn_h);
    cudaGetSymbolAddress((void**)&p_wal, g_wattn_l);
    cudaGetSymbolAddress((void**)&p_wph, g_wproj_h);
    cudaGetSymbolAddress((void**)&p_wpl, g_wproj_l);
    cudaGetSymbolAddress((void**)&p_wfh, g_wfc_h);
    cudaGetSymbolAddress((void**)&p_wfl, g_wfc_l);
    cudaGetSymbolAddress((void**)&p_w2h, g_wfc2_h);
    cudaGetSymbolAddress((void**)&p_w2l, g_wfc2_l);

    cudaFuncSetAttribute(flash_hmma, cudaFuncAttributeMaxDynamicSharedMemorySize, FLASH_SMEM);
    cudaFuncSetAttribute(hmma_gemm<1>, cudaFuncAttributeMaxDynamicSharedMemorySize, GEMM_SMEM);
    cudaFuncSetAttribute(hmma_gemm<2>, cudaFuncAttributeMaxDynamicSharedMemorySize, GEMM_SMEM);
    cudaFuncSetAttribute(hmma_gemm<3>, cudaFuncAttributeMaxDynamicSharedMemorySize, GEMM_SMEM);

    dim3 tb(32, 8);
    transpose_split_kernel<<<dim3(3 * C_DIM / 32, C_DIM / 32), tb>>>(W_attn, p_wah, p_wal, C_DIM, 3 * C_DIM);
    transpose_split_kernel<<<dim3(C_DIM / 32, C_DIM / 32), tb>>>(W_proj, p_wph, p_wpl, C_DIM, C_DIM);
    transpose_split_kernel<<<dim3(4 * C_DIM / 32, C_DIM / 32), tb>>>(W_fc, p_wfh, p_wfl, C_DIM, 4 * C_DIM);
    transpose_split_kernel<<<dim3(C_DIM / 32, 4 * C_DIM / 32), tb>>>(W_fc2, p_w2h, p_w2l, 4 * C_DIM, C_DIM);

    // 1. LN1 -> split
    ln_kernel<<<N_TOK, 256>>>(x, ln1_g, ln1_b, p_ah, p_al);
    // 2. QKV GEMM -> head-major q/k/v hi/lo planes (q pre-scaled)
    hmma_gemm<3><<<dim3(3 * C_DIM / 128, N_TOK / 128), 256, GEMM_SMEM>>>(
        p_ah, p_al, p_wah, p_wal, b_attn, nullptr, nullptr, nullptr, nullptr,
        p_qh, p_ql, p_kh, p_kl, p_vh, p_vl, N_TOK, 3 * C_DIM, C_DIM);
    // 3. Flash attention (HMMA) -> split y
    flash_hmma<<<dim3(T_SEQ / 128, B_SZ * NH), 256, FLASH_SMEM>>>(
        p_qh, p_ql, p_kh, p_kl, p_vh, p_vl, p_yh, p_yl);
    // 4. Proj GEMM + residual
    hmma_gemm<1><<<dim3(C_DIM / 128, N_TOK / 128), 256, GEMM_SMEM>>>(
        p_yh, p_yl, p_wph, p_wpl, b_proj, x, p_x2, nullptr, nullptr,
        nullptr, nullptr, nullptr, nullptr, nullptr, nullptr,
        N_TOK, C_DIM, C_DIM);
    // 5. LN2 -> split
    ln_kernel<<<N_TOK, 256>>>(p_x2, ln2_g, ln2_b, p_ah, p_al);
    // 6. FC GEMM + GELU -> split act
    hmma_gemm<2><<<dim3(4 * C_DIM / 128, N_TOK / 128), 256, GEMM_SMEM>>>(
        p_ah, p_al, p_wfh, p_wfl, b_fc, nullptr, nullptr, p_mh, p_ml,
        nullptr, nullptr, nullptr, nullptr, nullptr, nullptr,
        N_TOK, 4 * C_DIM, C_DIM);
    // 7. FC2 GEMM + residual -> final out
    hmma_gemm<1><<<dim3(C_DIM / 128, N_TOK / 128), 256, GEMM_SMEM>>>(
        p_mh, p_ml, p_w2h, p_w2l, b_fc2, p_x2, out, nullptr, nullptr,
        nullptr, nullptr, nullptr, nullptr, nullptr, nullptr,
        N_TOK, C_DIM, 4 * C_DIM);
}

// round 5
// speedup vs baseline: 3.6837x; 1.5236x over previous
#include <cuda_runtime.h>
#include <cuda_bf16.h>
#include <cuda_fp16.h>
#include <math.h>
#include <stdint.h>

// Problem constants
#define B_SZ   2
#define T_SEQ  2048
#define C_DIM  1024
#define NH     16
#define HDIM   64
#define N_TOK  (B_SZ * T_SEQ)   // 4096

// ---------------------------------------------------------------------------
// Scratch (device globals; runtime alloc is forbidden)
// ---------------------------------------------------------------------------
__device__ float         g_x2_buf [N_TOK * C_DIM];         // x after attn residual
__device__ __nv_bfloat16 g_ah[N_TOK * C_DIM];              // LN1 out hi
__device__ __nv_bfloat16 g_al[N_TOK * C_DIM];              // LN1 out lo
__device__ __half        g_y16[N_TOK * C_DIM];             // attn out (fp16)
__device__ __half        g_a16[N_TOK * C_DIM];             // LN2 out (fp16)
__device__ __half        g_m16[N_TOK * 4 * C_DIM];         // gelu act (fp16)
// Q/K/V head-major planes [(b*NH+h)][t][64], hi/lo. Q pre-scaled by 1/8.
__device__ __nv_bfloat16 g_q_h[N_TOK * C_DIM], g_q_l[N_TOK * C_DIM];
__device__ __nv_bfloat16 g_k_h[N_TOK * C_DIM], g_k_l[N_TOK * C_DIM];
__device__ __nv_bfloat16 g_v_h[N_TOK * C_DIM], g_v_l[N_TOK * C_DIM];
// Transposed weights: Wt[n*K + k] = W[k*N + n]
__device__ __nv_bfloat16 g_wattn_h[3 * C_DIM * C_DIM], g_wattn_l[3 * C_DIM * C_DIM];
__device__ __half        g_wproj16[C_DIM * C_DIM];
__device__ __half        g_wfc16  [4 * C_DIM * C_DIM];
__device__ __half        g_wfc216 [C_DIM * 4 * C_DIM];

// ---------------------------------------------------------------------------
// Helpers
// ---------------------------------------------------------------------------
__device__ __forceinline__ float gelu_tanh(float v) {
    float v3 = v * v * v;
    return 0.5f * v * (1.0f + tanhf(0.7978845608028654f * (v + 0.044715f * v3)));
}

__device__ __forceinline__ void split_bf16(float v, __nv_bfloat16& h, __nv_bfloat16& l) {
    h = __float2bfloat16(v);
    l = __float2bfloat16(v - __bfloat162float(h));
}

// Fast exp on the FMA pipe (no MUFU). Valid for x <= 0 (softmax args).
__device__ __forceinline__ float fexp(float x) {
    float t = fmaxf(x * 1.4426950408889634f, -126.0f);
    float fi = t + 12582912.0f;
    int   ii = __float_as_int(fi) - 0x4B400000;
    float f  = t - (fi - 12582912.0f);
    float p  = 1.3333558146e-3f;
    p = fmaf(p, f, 9.6181291056e-3f);
    p = fmaf(p, f, 5.5504108664e-2f);
    p = fmaf(p, f, 2.4022650696e-1f);
    p = fmaf(p, f, 6.9314718056e-1f);
    p = fmaf(p, f, 1.0f);
    return __int_as_float((ii + 127) << 23) * p;
}

__device__ __forceinline__ uint32_t smem_u32(const void* p) {
    uint32_t a;
    asm("{ .reg .u64 t; cvta.to.shared.u64 t, %1; cvt.u32.u64 %0, t; }" : "=r"(a) : "l"(p));
    return a;
}

__device__ __forceinline__ void ldm_x4(uint32_t* r, uint32_t addr) {
    asm volatile("ldmatrix.sync.aligned.m8n8.x4.shared.b16 {%0,%1,%2,%3}, [%4];"
                 : "=r"(r[0]), "=r"(r[1]), "=r"(r[2]), "=r"(r[3]) : "r"(addr));
}

__device__ __forceinline__ void ldm_x4t(uint32_t* r, uint32_t addr) {
    asm volatile("ldmatrix.sync.aligned.m8n8.x4.trans.shared.b16 {%0,%1,%2,%3}, [%4];"
                 : "=r"(r[0]), "=r"(r[1]), "=r"(r[2]), "=r"(r[3]) : "r"(addr));
}

__device__ __forceinline__ void mma_bf16(float* c, const uint32_t* a, const uint32_t* b) {
    asm volatile(
        "mma.sync.aligned.m16n8k16.row.col.f32.bf16.bf16.f32 "
        "{%0,%1,%2,%3}, {%4,%5,%6,%7}, {%8,%9}, {%0,%1,%2,%3};"
        : "+f"(c[0]), "+f"(c[1]), "+f"(c[2]), "+f"(c[3])
        : "r"(a[0]), "r"(a[1]), "r"(a[2]), "r"(a[3]), "r"(b[0]), "r"(b[1]));
}

__device__ __forceinline__ void mma_f16(float* c, const uint32_t* a, const uint32_t* b) {
    asm volatile(
        "mma.sync.aligned.m16n8k16.row.col.f32.f16.f16.f32 "
        "{%0,%1,%2,%3}, {%4,%5,%6,%7}, {%8,%9}, {%0,%1,%2,%3};"
        : "+f"(c[0]), "+f"(c[1]), "+f"(c[2]), "+f"(c[3])
        : "r"(a[0]), "r"(a[1]), "r"(a[2]), "r"(a[3]), "r"(b[0]), "r"(b[1]));
}

__device__ __forceinline__ void cp16(uint32_t saddr, const void* g) {
    asm volatile("cp.async.cg.shared.global [%0], [%1], 16;" :: "r"(saddr), "l"(g));
}
#define CP_COMMIT() asm volatile("cp.async.commit_group;")
#define CP_WAIT(n)  asm volatile("cp.async.wait_group %0;" :: "n"(n))

__device__ __forceinline__ uint32_t pack_bf2(__nv_bfloat16 a, __nv_bfloat16 b) {
    __nv_bfloat162 t{a, b};
    return *reinterpret_cast<uint32_t*>(&t);
}

// GEMM smem tile geometry: 128 rows x 32 elems (16-bit), row stride 40 elems
#define T_STRIDE   40
#define T_ROWB     80
#define T_BYTES    10240
#define BUF_BYTES  (4 * T_BYTES)
#define GEMM_SMEM  (2 * BUF_BYTES)       // 81920 (bf16 3-pass: 4 tiles x2 bufs)
#define BUF2_BYTES (2 * T_BYTES)
#define GEMM_SMEM16 (2 * BUF2_BYTES)     // 40960 (fp16 1-pass: 2 tiles x2 bufs)

// ---------------------------------------------------------------------------
// Weight transpose kernels
// ---------------------------------------------------------------------------
__global__ __launch_bounds__(256) void transpose_split_kernel(
    const float* __restrict__ W, __nv_bfloat16* __restrict__ Th,
    __nv_bfloat16* __restrict__ Tl, int K, int N)
{
    __shared__ float t[32][33];
    int n0 = blockIdx.x * 32, k0 = blockIdx.y * 32;
    int tx = threadIdx.x, ty = threadIdx.y;
    #pragma unroll
    for (int i = 0; i < 4; i++)
        t[ty + 8 * i][tx] = W[(size_t)(k0 + ty + 8 * i) * N + n0 + tx];
    __syncthreads();
    #pragma unroll
    for (int i = 0; i < 4; i++) {
        float v = t[tx][ty + 8 * i];
        __nv_bfloat16 h, l;
        split_bf16(v, h, l);
        size_t o = (size_t)(n0 + ty + 8 * i) * K + k0 + tx;
        Th[o] = h;
        Tl[o] = l;
    }
}

__global__ __launch_bounds__(256) void transpose_f16_kernel(
    const float* __restrict__ W, __half* __restrict__ T16, int K, int N)
{
    __shared__ float t[32][33];
    int n0 = blockIdx.x * 32, k0 = blockIdx.y * 32;
    int tx = threadIdx.x, ty = threadIdx.y;
    #pragma unroll
    for (int i = 0; i < 4; i++)
        t[ty + 8 * i][tx] = W[(size_t)(k0 + ty + 8 * i) * N + n0 + tx];
    __syncthreads();
    #pragma unroll
    for (int i = 0; i < 4; i++) {
        size_t o = (size_t)(n0 + ty + 8 * i) * K + k0 + tx;
        T16[o] = __float2half_rn(t[tx][ty + 8 * i]);
    }
}

// ---------------------------------------------------------------------------
// LayerNorm. MODE 0: bf16 hi/lo out. MODE 1: fp16 out.
// ---------------------------------------------------------------------------
template<int MODE>
__global__ __launch_bounds__(256) void ln_kernel(
    const float* __restrict__ x, const float* __restrict__ g,
    const float* __restrict__ b, __nv_bfloat16* __restrict__ oh,
    __nv_bfloat16* __restrict__ ol, __half* __restrict__ o16)
{
    __shared__ float red[8];
    int row = blockIdx.x;
    int tid = threadIdx.x;
    const float4* x4 = (const float4*)(x + (size_t)row * C_DIM);
    float4 v = x4[tid];

    float s = v.x + v.y + v.z + v.w;
    #pragma unroll
    for (int o = 16; o; o >>= 1) s += __shfl_xor_sync(0xffffffffu, s, o);
    if ((tid & 31) == 0) red[tid >> 5] = s;
    __syncthreads();
    s = red[0] + red[1] + red[2] + red[3] + red[4] + red[5] + red[6] + red[7];
    float mu = s * (1.0f / C_DIM);

    float dx0 = v.x - mu, dx1 = v.y - mu, dx2 = v.z - mu, dx3 = v.w - mu;
    float q = dx0*dx0 + dx1*dx1 + dx2*dx2 + dx3*dx3;
    #pragma unroll
    for (int o = 16; o; o >>= 1) q += __shfl_xor_sync(0xffffffffu, q, o);
    __syncthreads();
    if ((tid & 31) == 0) red[tid >> 5] = q;
    __syncthreads();
    q = red[0] + red[1] + red[2] + red[3] + red[4] + red[5] + red[6] + red[7];
    float rs = rsqrtf(q * (1.0f / C_DIM) + 1e-5f);

    float4 gg = ((const float4*)g)[tid];
    float4 bb = ((const float4*)b)[tid];
    float o0 = dx0 * rs * gg.x + bb.x;
    float o1 = dx1 * rs * gg.y + bb.y;
    float o2 = dx2 * rs * gg.z + bb.z;
    float o3 = dx3 * rs * gg.w + bb.w;

    size_t base = (size_t)row * C_DIM + tid * 4;
    if (MODE == 0) {
        __nv_bfloat16 h0,h1,h2,h3,l0,l1,l2,l3;
        split_bf16(o0,h0,l0); split_bf16(o1,h1,l1);
        split_bf16(o2,h2,l2); split_bf16(o3,h3,l3);
        ((__nv_bfloat162*)(oh + base))[0] = __nv_bfloat162{h0, h1};
        ((__nv_bfloat162*)(oh + base))[1] = __nv_bfloat162{h2, h3};
        ((__nv_bfloat162*)(ol + base))[0] = __nv_bfloat162{l0, l1};
        ((__nv_bfloat162*)(ol + base))[1] = __nv_bfloat162{l2, l3};
    } else {
        ((__half2*)(o16 + base))[0] = __half2{__float2half_rn(o0), __float2half_rn(o1)};
        ((__half2*)(o16 + base))[1] = __half2{__float2half_rn(o2), __float2half_rn(o3)};
    }
}

// ---------------------------------------------------------------------------
// bf16 3-pass HMMA GEMM, QKV epilogue only (head-major hi/lo planes).
// ---------------------------------------------------------------------------
__global__ __launch_bounds__(256) void hmma_gemm_qkv(
    const __nv_bfloat16* __restrict__ Ahi, const __nv_bfloat16* __restrict__ Alo,
    const __nv_bfloat16* __restrict__ Bhi, const __nv_bfloat16* __restrict__ Blo,
    const float* __restrict__ bias,
    __nv_bfloat16* __restrict__ q_h, __nv_bfloat16* __restrict__ q_l,
    __nv_bfloat16* __restrict__ k_h, __nv_bfloat16* __restrict__ k_l,
    __nv_bfloat16* __restrict__ v_h, __nv_bfloat16* __restrict__ v_l,
    int M, int N, int K)
{
    extern __shared__ char smem[];
    uint32_t sb = smem_u32(smem);
    int tid = threadIdx.x, lane = tid & 31, w = tid >> 5;
    int wm = w >> 2, wn = w & 3;
    int m0 = blockIdx.y * 128, n0 = blockIdx.x * 128;

    const __nv_bfloat16* srcs[4] = {
        Ahi + (size_t)m0 * K, Alo + (size_t)m0 * K,
        Bhi + (size_t)n0 * K, Blo + (size_t)n0 * K };

    float acc[4][4][4];
    #pragma unroll
    for (int a = 0; a < 4; a++)
        #pragma unroll
        for (int b = 0; b < 4; b++)
            #pragma unroll
            for (int c = 0; c < 4; c++) acc[a][b][c] = 0.0f;

    const int nch = K >> 5;

    #pragma unroll
    for (int t = 0; t < 4; t++) {
        #pragma unroll
        for (int u = 0; u < 2; u++) {
            int idx = tid + 256 * u;
            int r = idx >> 2, c = idx & 3;
            cp16(sb + t * T_BYTES + r * T_ROWB + c * 16, srcs[t] + (size_t)r * K + c * 8);
        }
    }
    CP_COMMIT();

    for (int ch = 0; ch < nch; ch++) {
        uint32_t buf = sb + (ch & 1) * BUF_BYTES;
        if (ch + 1 < nch) {
            uint32_t nbuf = sb + ((ch + 1) & 1) * BUF_BYTES;
            int k0 = (ch + 1) << 5;
            #pragma unroll
            for (int t = 0; t < 4; t++) {
                #pragma unroll
                for (int u = 0; u < 2; u++) {
                    int idx = tid + 256 * u;
                    int r = idx >> 2, c = idx & 3;
                    cp16(nbuf + t * T_BYTES + r * T_ROWB + c * 16,
                         srcs[t] + (size_t)r * K + k0 + c * 8);
                }
            }
            CP_COMMIT();
            CP_WAIT(1);
        } else {
            CP_WAIT(0);
        }
        __syncthreads();

        uint32_t abase = buf;
        uint32_t bbase = buf + 2 * T_BYTES;
        int arow = (lane & 7) + ((lane >> 3) & 1) * 8;
        int akof = ((lane >> 4) & 1) * 8;
        int brow = (lane & 7) + ((lane >> 4) & 1) * 8;
        int bkof = ((lane >> 3) & 1) * 8;

        #pragma unroll
        for (int ks = 0; ks < 2; ks++) {
            uint32_t Ah[4][4], Al[4][4], Bh[4][2], Bl[4][2];
            #pragma unroll
            for (int mf = 0; mf < 4; mf++) {
                uint32_t ad = abase + (uint32_t)(((wm * 64 + mf * 16 + arow) * T_STRIDE
                                                 + ks * 16 + akof) * 2);
                ldm_x4(Ah[mf], ad);
                ldm_x4(Al[mf], ad + T_BYTES);
            }
            #pragma unroll
            for (int np = 0; np < 2; np++) {
                uint32_t bd = bbase + (uint32_t)(((wn * 32 + np * 16 + brow) * T_STRIDE
                                                 + ks * 16 + bkof) * 2);
                uint32_t th[4], tl[4];
                ldm_x4(th, bd);
                ldm_x4(tl, bd + T_BYTES);
                Bh[np*2][0]=th[0]; Bh[np*2][1]=th[1]; Bh[np*2+1][0]=th[2]; Bh[np*2+1][1]=th[3];
                Bl[np*2][0]=tl[0]; Bl[np*2][1]=tl[1]; Bl[np*2+1][0]=tl[2]; Bl[np*2+1][1]=tl[3];
            }
            #pragma unroll
            for (int mf = 0; mf < 4; mf++)
                #pragma unroll
                for (int nf = 0; nf < 4; nf++)
                    mma_bf16(acc[mf][nf], Ah[mf], Bh[nf]);
            #pragma unroll
            for (int mf = 0; mf < 4; mf++)
                #pragma unroll
                for (int nf = 0; nf < 4; nf++)
                    mma_bf16(acc[mf][nf], Ah[mf], Bl[nf]);
            #pragma unroll
            for (int mf = 0; mf < 4; mf++)
                #pragma unroll
                for (int nf = 0; nf < 4; nf++)
                    mma_bf16(acc[mf][nf], Al[mf], Bh[nf]);
        }
        __syncthreads();
    }

    int qr = lane >> 2;
    int qc = (lane & 3) * 2;
    #pragma unroll
    for (int mf = 0; mf < 4; mf++) {
        #pragma unroll
        for (int nf = 0; nf < 4; nf++) {
            int col = n0 + wn * 32 + nf * 8 + qc;
            float b0 = bias[col], b1 = bias[col + 1];
            #pragma unroll
            for (int half = 0; half < 2; half++) {
                int row = m0 + wm * 64 + mf * 16 + qr + half * 8;
                float v0 = acc[mf][nf][half * 2 + 0] + b0;
                float v1 = acc[mf][nf][half * 2 + 1] + b1;
                int sec = col >> 10;
                int within = col & 1023;
                int hd = within >> 6, d = within & 63;
                if (sec == 0) { v0 *= 0.125f; v1 *= 0.125f; }
                __nv_bfloat16 h0, l0, h1, l1;
                split_bf16(v0, h0, l0);
                split_bf16(v1, h1, l1);
                size_t gi = ((size_t)((row >> 11) * NH + hd) * T_SEQ + (row & 2047)) * 64 + d;
                __nv_bfloat16* dh = (sec == 0) ? q_h : (sec == 1) ? k_h : v_h;
                __nv_bfloat16* dl = (sec == 0) ? q_l : (sec == 1) ? k_l : v_l;
                *(__nv_bfloat162*)(dh + gi) = __nv_bfloat162{h0, h1};
                *(__nv_bfloat162*)(dl + gi) = __nv_bfloat162{l0, l1};
            }
        }
    }
}

// ---------------------------------------------------------------------------
// fp16 1-pass HMMA GEMM: D = A[M,K] @ B[N,K]^T.
// EPI 1: fp32 out + bias + res. EPI 2: gelu -> fp16 out.
// ---------------------------------------------------------------------------
template<int EPI>
__global__ __launch_bounds__(256) void hmma_gemm_f16(
    const __half* __restrict__ A, const __half* __restrict__ B,
    const float* __restrict__ bias, const float* __restrict__ res,
    float* __restrict__ outf, __half* __restrict__ o16,
    int M, int N, int K)
{
    extern __shared__ char smem[];
    uint32_t sb = smem_u32(smem);
    int tid = threadIdx.x, lane = tid & 31, w = tid >> 5;
    int wm = w >> 2, wn = w & 3;
    int m0 = blockIdx.y * 128, n0 = blockIdx.x * 128;

    const __half* srcs[2] = { A + (size_t)m0 * K, B + (size_t)n0 * K };

    float acc[4][4][4];
    #pragma unroll
    for (int a = 0; a < 4; a++)
        #pragma unroll
        for (int b = 0; b < 4; b++)
            #pragma unroll
            for (int c = 0; c < 4; c++) acc[a][b][c] = 0.0f;

    const int nch = K >> 5;

    #pragma unroll
    for (int t = 0; t < 2; t++) {
        #pragma unroll
        for (int u = 0; u < 2; u++) {
            int idx = tid + 256 * u;
            int r = idx >> 2, c = idx & 3;
            cp16(sb + t * T_BYTES + r * T_ROWB + c * 16, srcs[t] + (size_t)r * K + c * 8);
        }
    }
    CP_COMMIT();

    for (int ch = 0; ch < nch; ch++) {
        uint32_t buf = sb + (ch & 1) * BUF2_BYTES;
        if (ch + 1 < nch) {
            uint32_t nbuf = sb + ((ch + 1) & 1) * BUF2_BYTES;
            int k0 = (ch + 1) << 5;
            #pragma unroll
            for (int t = 0; t < 2; t++) {
                #pragma unroll
                for (int u = 0; u < 2; u++) {
                    int idx = tid + 256 * u;
                    int r = idx >> 2, c = idx & 3;
                    cp16(nbuf + t * T_BYTES + r * T_ROWB + c * 16,
                         srcs[t] + (size_t)r * K + k0 + c * 8);
                }
            }
            CP_COMMIT();
            CP_WAIT(1);
        } else {
            CP_WAIT(0);
        }
        __syncthreads();

        uint32_t abase = buf;
        uint32_t bbase = buf + T_BYTES;
        int arow = (lane & 7) + ((lane >> 3) & 1) * 8;
        int akof = ((lane >> 4) & 1) * 8;
        int brow = (lane & 7) + ((lane >> 4) & 1) * 8;
        int bkof = ((lane >> 3) & 1) * 8;

        #pragma unroll
        for (int ks = 0; ks < 2; ks++) {
            uint32_t Af[4][4], Bf[4][2];
            #pragma unroll
            for (int mf = 0; mf < 4; mf++) {
                uint32_t ad = abase + (uint32_t)(((wm * 64 + mf * 16 + arow) * T_STRIDE
                                                 + ks * 16 + akof) * 2);
                ldm_x4(Af[mf], ad);
            }
            #pragma unroll
            for (int np = 0; np < 2; np++) {
                uint32_t bd = bbase + (uint32_t)(((wn * 32 + np * 16 + brow) * T_STRIDE
                                                 + ks * 16 + bkof) * 2);
                uint32_t th[4];
                ldm_x4(th, bd);
                Bf[np*2][0]=th[0]; Bf[np*2][1]=th[1]; Bf[np*2+1][0]=th[2]; Bf[np*2+1][1]=th[3];
            }
            #pragma unroll
            for (int mf = 0; mf < 4; mf++)
                #pragma unroll
                for (int nf = 0; nf < 4; nf++)
                    mma_f16(acc[mf][nf], Af[mf], Bf[nf]);
        }
        __syncthreads();
    }

    int qr = lane >> 2;
    int qc = (lane & 3) * 2;
    #pragma unroll
    for (int mf = 0; mf < 4; mf++) {
        #pragma unroll
        for (int nf = 0; nf < 4; nf++) {
            int col = n0 + wn * 32 + nf * 8 + qc;
            float b0 = bias[col], b1 = bias[col + 1];
            #pragma unroll
            for (int half = 0; half < 2; half++) {
                int row = m0 + wm * 64 + mf * 16 + qr + half * 8;
                float v0 = acc[mf][nf][half * 2 + 0] + b0;
                float v1 = acc[mf][nf][half * 2 + 1] + b1;
                size_t gi = (size_t)row * N + col;
                if (EPI == 1) {
                    float2 rv = *(const float2*)(res + gi);
                    v0 += rv.x; v1 += rv.y;
                    *(float2*)(outf + gi) = make_float2(v0, v1);
                } else {
                    v0 = gelu_tanh(v0);
                    v1 = gelu_tanh(v1);
                    *(__half2*)(o16 + gi) = __half2{__float2half_rn(v0), __float2half_rn(v1)};
                }
            }
        }
    }
}

// ---------------------------------------------------------------------------
// Flash attention, HMMA bf16 3-pass, causal, HD=64. Output fp16.
// ---------------------------------------------------------------------------
#define FQT   144
#define FQSZ  (128 * FQT * 2)
#define FTSZ  (64 * FQT)
#define FKVSZ (4 * FTSZ)
#define FLASH_SMEM (FQSZ + 2 * FKVSZ)  // 110592

__global__ __launch_bounds__(256) void flash_hmma(
    const __nv_bfloat16* __restrict__ qh, const __nv_bfloat16* __restrict__ ql,
    const __nv_bfloat16* __restrict__ kh, const __nv_bfloat16* __restrict__ kl,
    const __nv_bfloat16* __restrict__ vh, const __nv_bfloat16* __restrict__ vl,
    __half* __restrict__ y16)
{
    extern __shared__ char smf[];
    uint32_t sb = smem_u32(smf);
    int tid = threadIdx.x, lane = tid & 31, w = tid >> 5;
    int bh = blockIdx.y;
    int qb = blockIdx.x * 128;
    size_t plane = (size_t)bh * (T_SEQ * 64);

    const __nv_bfloat16* qs[2] = { qh + plane + (size_t)qb * 64, ql + plane + (size_t)qb * 64 };
    const __nv_bfloat16* ks[4] = { kh + plane, kl + plane, vh + plane, vl + plane };

    #pragma unroll
    for (int u = 0; u < 8; u++) {
        int idx = tid + 256 * u;
        int t = idx >> 10, r = (idx >> 3) & 127, c = idx & 7;
        cp16(sb + t * (128 * FQT) + r * FQT + c * 16, qs[t] + (size_t)r * 64 + c * 8);
    }
    CP_COMMIT();
    #pragma unroll
    for (int u = 0; u < 8; u++) {
        int idx = tid + 256 * u;
        int t = idx >> 9, r = (idx >> 3) & 63, c = idx & 7;
        cp16(sb + FQSZ + t * FTSZ + r * FQT + c * 16, ks[t] + (size_t)r * 64 + c * 8);
    }
    CP_COMMIT();
    CP_WAIT(1);
    __syncthreads();

    int arow = (lane & 7) + ((lane >> 3) & 1) * 8;
    int akof = ((lane >> 4) & 1) * 8;
    uint32_t QHf[4][4], QLf[4][4];
    #pragma unroll
    for (int kc = 0; kc < 4; kc++) {
        uint32_t ad = sb + (uint32_t)((w * 16 + arow) * FQT + (kc * 16 + akof) * 2);
        ldm_x4(QHf[kc], ad);
        ldm_x4(QLf[kc], ad + 128 * FQT);
    }

    float oacc[8][4];
    #pragma unroll
    for (int j = 0; j < 8; j++)
        #pragma unroll
        for (int c = 0; c < 4; c++) oacc[j][c] = 0.0f;
    float m_run[2] = { -1e30f, -1e30f };
    float l_run[2] = { 0.0f, 0.0f };

    int brow = (lane & 7) + ((lane >> 4) & 1) * 8;
    int bkof = ((lane >> 3) & 1) * 8;
    int vrow = (lane & 7) + ((lane >> 3) & 1) * 8;
    int vcol = ((lane >> 4) & 1) * 8;

    const int nkv = (qb >> 6) + 2;
    for (int it = 0; it < nkv; it++) {
        if (it + 1 < nkv) {
            int kb2 = (it + 1) << 6;
            uint32_t nb_ = sb + FQSZ + ((it + 1) & 1) * FKVSZ;
            #pragma unroll
            for (int u = 0; u < 8; u++) {
                int idx = tid + 256 * u;
                int t = idx >> 9, r = (idx >> 3) & 63, c = idx & 7;
                cp16(nb_ + t * FTSZ + r * FQT + c * 16, ks[t] + (size_t)(kb2 + r) * 64 + c * 8);
            }
            CP_COMMIT();
            CP_WAIT(1);
        } else {
            CP_WAIT(0);
        }
        __syncthreads();
        uint32_t kvb = sb + FQSZ + (it & 1) * FKVSZ;

        float sacc[8][4];
        #pragma unroll
        for (int j = 0; j < 8; j++)
            #pragma unroll
            for (int c = 0; c < 4; c++) sacc[j][c] = 0.0f;

        #pragma unroll
        for (int kc = 0; kc < 4; kc++) {
            #pragma unroll
            for (int nb2 = 0; nb2 < 4; nb2++) {
                uint32_t ad = kvb + (uint32_t)((nb2 * 16 + brow) * FQT + (kc * 16 + bkof) * 2);
                uint32_t th[4], tl[4];
                ldm_x4(th, ad);
                ldm_x4(tl, ad + FTSZ);
                uint32_t bh0[2] = { th[0], th[1] }, bh1[2] = { th[2], th[3] };
                uint32_t bl0[2] = { tl[0], tl[1] }, bl1[2] = { tl[2], tl[3] };
                mma_bf16(sacc[nb2*2],   QHf[kc], bh0);
                mma_bf16(sacc[nb2*2+1], QHf[kc], bh1);
                mma_bf16(sacc[nb2*2],   QHf[kc], bl0);
                mma_bf16(sacc[nb2*2+1], QHf[kc], bl1);
                mma_bf16(sacc[nb2*2],   QLf[kc], bh0);
                mma_bf16(sacc[nb2*2+1], QLf[kc], bh1);
            }
        }

        int kb = it << 6;
        int qrow = qb + w * 16 + (lane >> 2);
        if (kb + 63 > qb + w * 16) {
            #pragma unroll
            for (int j = 0; j < 8; j++) {
                int col = kb + j * 8 + (lane & 3) * 2;
                #pragma unroll
                for (int rh = 0; rh < 2; rh++) {
                    int row = qrow + rh * 8;
                    if (col     > row) sacc[j][rh*2]   = -1e30f;
                    if (col + 1 > row) sacc[j][rh*2+1] = -1e30f;
                }
            }
        }

        #pragma unroll
        for (int rh = 0; rh < 2; rh++) {
            float mt = -1e30f;
            #pragma unroll
            for (int j = 0; j < 8; j++) {
                mt = fmaxf(mt, sacc[j][rh*2]);
                mt = fmaxf(mt, sacc[j][rh*2+1]);
            }
            mt = fmaxf(mt, __shfl_xor_sync(0xffffffffu, mt, 1));
            mt = fmaxf(mt, __shfl_xor_sync(0xffffffffu, mt, 2));
            float m_new = fmaxf(m_run[rh], mt);
            float alpha = fexp(m_run[rh] - m_new);
            m_run[rh] = m_new;
            float sum = 0.0f;
            #pragma unroll
            for (int j = 0; j < 8; j++) {
                float p0 = fexp(sacc[j][rh*2]   - m_new);
                float p1 = fexp(sacc[j][rh*2+1] - m_new);
                sacc[j][rh*2]   = p0;
                sacc[j][rh*2+1] = p1;
                sum += p0 + p1;
            }
            sum += __shfl_xor_sync(0xffffffffu, sum, 1);
            sum += __shfl_xor_sync(0xffffffffu, sum, 2);
            l_run[rh] = l_run[rh] * alpha + sum;
            #pragma unroll
            for (int j = 0; j < 8; j++) {
                oacc[j][rh*2]   *= alpha;
                oacc[j][rh*2+1] *= alpha;
            }
        }

        uint32_t PH[4][4], PL[4][4];
        #pragma unroll
        for (int kc = 0; kc < 4; kc++) {
            #pragma unroll
            for (int q4 = 0; q4 < 4; q4++) {
                int j  = kc * 2 + (q4 >> 1);
                int rh = q4 & 1;
                float p0 = sacc[j][rh*2], p1 = sacc[j][rh*2+1];
                __nv_bfloat16 h0, l0, h1, l1;
                split_bf16(p0, h0, l0);
                split_bf16(p1, h1, l1);
                PH[kc][q4] = pack_bf2(h0, h1);
                PL[kc][q4] = pack_bf2(l0, l1);
            }
        }

        #pragma unroll
        for (int kc = 0; kc < 4; kc++) {
            #pragma unroll
            for (int nb2 = 0; nb2 < 4; nb2++) {
                uint32_t ad = kvb + 2 * FTSZ
                            + (uint32_t)((kc * 16 + vrow) * FQT + (nb2 * 16 + vcol) * 2);
                uint32_t th[4], tl[4];
                ldm_x4t(th, ad);
                ldm_x4t(tl, ad + FTSZ);
                uint32_t bh0[2] = { th[0], th[1] }, bh1[2] = { th[2], th[3] };
                uint32_t bl0[2] = { tl[0], tl[1] }, bl1[2] = { tl[2], tl[3] };
                mma_bf16(oacc[nb2*2],   PH[kc], bh0);
                mma_bf16(oacc[nb2*2+1], PH[kc], bh1);
                mma_bf16(oacc[nb2*2],   PH[kc], bl0);
                mma_bf16(oacc[nb2*2+1], PH[kc], bl1);
                mma_bf16(oacc[nb2*2],   PL[kc], bh0);
                mma_bf16(oacc[nb2*2+1], PL[kc], bh1);
            }
        }
        __syncthreads();
    }

    float inv0 = 1.0f / l_run[0];
    float inv1 = 1.0f / l_run[1];
    int b = bh >> 4, h = bh & 15;
    #pragma unroll
    for (int j = 0; j < 8; j++) {
        #pragma unroll
        for (int rh = 0; rh < 2; rh++) {
            float iv = rh ? inv1 : inv0;
            float o0 = oacc[j][rh*2]   * iv;
            float o1 = oacc[j][rh*2+1] * iv;
            size_t row = (size_t)b * T_SEQ + qb + w * 16 + (lane >> 2) + rh * 8;
            size_t gi = row * C_DIM + h * 64 + j * 8 + (lane & 3) * 2;
            *(__half2*)(y16 + gi) = __half2{__float2half_rn(o0), __float2half_rn(o1)};
        }
    }
}

// ---------------------------------------------------------------------------
// Launch
// ---------------------------------------------------------------------------
extern "C" void kernel_launch(void* const* d_in, const int* in_sizes, int n_in,
                              void* d_out, int out_size)
{
    const float* x      = (const float*)d_in[0];
    const float* ln1_g  = (const float*)d_in[1];
    const float* ln1_b  = (const float*)d_in[2];
    const float* W_attn = (const float*)d_in[3];
    const float* b_attn = (const float*)d_in[4];
    const float* W_proj = (const float*)d_in[5];
    const float* b_proj = (const float*)d_in[6];
    const float* ln2_g  = (const float*)d_in[7];
    const float* ln2_b  = (const float*)d_in[8];
    const float* W_fc   = (const float*)d_in[9];
    const float* b_fc   = (const float*)d_in[10];
    const float* W_fc2  = (const float*)d_in[11];
    const float* b_fc2  = (const float*)d_in[12];
    float* out = (float*)d_out;

    float *p_x2;
    __nv_bfloat16 *p_ah, *p_al;
    __half *p_y16, *p_a16, *p_m16, *p_wp16, *p_wf16, *p_w216;
    __nv_bfloat16 *p_qh, *p_ql, *p_kh, *p_kl, *p_vh, *p_vl;
    __nv_bfloat16 *p_wah, *p_wal;
    cudaGetSymbolAddress((void**)&p_x2,  g_x2_buf);
    cudaGetSymbolAddress((void**)&p_ah,  g_ah);
    cudaGetSymbolAddress((void**)&p_al,  g_al);
    cudaGetSymbolAddress((void**)&p_y16, g_y16);
    cudaGetSymbolAddress((void**)&p_a16, g_a16);
    cudaGetSymbolAddress((void**)&p_m16, g_m16);
    cudaGetSymbolAddress((void**)&p_qh,  g_q_h);
    cudaGetSymbolAddress((void**)&p_ql,  g_q_l);
    cudaGetSymbolAddress((void**)&p_kh,  g_k_h);
    cudaGetSymbolAddress((void**)&p_kl,  g_k_l);
    cudaGetSymbolAddress((void**)&p_vh,  g_v_h);
    cudaGetSymbolAddress((void**)&p_vl,  g_v_l);
    cudaGetSymbolAddress((void**)&p_wah, g_wattn_h);
    cudaGetSymbolAddress((void**)&p_wal, g_wattn_l);
    cudaGetSymbolAddress((void**)&p_wp16, g_wproj16);
    cudaGetSymbolAddress((void**)&p_wf16, g_wfc16);
    cudaGetSymbolAddress((void**)&p_w216, g_wfc216);

    cudaFuncSetAttribute(flash_hmma, cudaFuncAttributeMaxDynamicSharedMemorySize, FLASH_SMEM);
    cudaFuncSetAttribute(hmma_gemm_qkv, cudaFuncAttributeMaxDynamicSharedMemorySize, GEMM_SMEM);
    cudaFuncSetAttribute(hmma_gemm_f16<1>, cudaFuncAttributeMaxDynamicSharedMemorySize, GEMM_SMEM16);
    cudaFuncSetAttribute(hmma_gemm_f16<2>, cudaFuncAttributeMaxDynamicSharedMemorySize, GEMM_SMEM16);

    dim3 tb(32, 8);
    transpose_split_kernel<<<dim3(3 * C_DIM / 32, C_DIM / 32), tb>>>(W_attn, p_wah, p_wal, C_DIM, 3 * C_DIM);
    transpose_f16_kernel<<<dim3(C_DIM / 32, C_DIM / 32), tb>>>(W_proj, p_wp16, C_DIM, C_DIM);
    transpose_f16_kernel<<<dim3(4 * C_DIM / 32, C_DIM / 32), tb>>>(W_fc, p_wf16, C_DIM, 4 * C_DIM);
    transpose_f16_kernel<<<dim3(C_DIM / 32, 4 * C_DIM / 32), tb>>>(W_fc2, p_w216, 4 * C_DIM, C_DIM);

    // 1. LN1 -> bf16 split
    ln_kernel<0><<<N_TOK, 256>>>(x, ln1_g, ln1_b, p_ah, p_al, nullptr);
    // 2. QKV GEMM (bf16 3-pass) -> head-major q/k/v hi/lo planes
    hmma_gemm_qkv<<<dim3(3 * C_DIM / 128, N_TOK / 128), 256, GEMM_SMEM>>>(
        p_ah, p_al, p_wah, p_wal, b_attn,
        p_qh, p_ql, p_kh, p_kl, p_vh, p_vl, N_TOK, 3 * C_DIM, C_DIM);
    // 3. Flash attention (bf16 3-pass) -> y fp16
    flash_hmma<<<dim3(T_SEQ / 128, B_SZ * NH), 256, FLASH_SMEM>>>(
        p_qh, p_ql, p_kh, p_kl, p_vh, p_vl, p_y16);
    // 4. Proj GEMM (fp16 1-pass) + residual -> x2 fp32
    hmma_gemm_f16<1><<<dim3(C_DIM / 128, N_TOK / 128), 256, GEMM_SMEM16>>>(
        p_y16, p_wp16, b_proj, x, p_x2, nullptr, N_TOK, C_DIM, C_DIM);
    // 5. LN2 -> fp16
    ln_kernel<1><<<N_TOK, 256>>>(p_x2, ln2_g, ln2_b, nullptr, nullptr, p_a16);
    // 6. FC GEMM (fp16 1-pass) + GELU -> fp16 act
    hmma_gemm_f16<2><<<dim3(4 * C_DIM / 128, N_TOK / 128), 256, GEMM_SMEM16>>>(
        p_a16, p_wf16, b_fc, nullptr, nullptr, p_m16, N_TOK, 4 * C_DIM, C_DIM);
    // 7. FC2 GEMM (fp16 1-pass) + residual -> final out
    hmma_gemm_f16<1><<<dim3(C_DIM / 128, N_TOK / 128), 256, GEMM_SMEM16>>>(
        p_m16, p_w216, b_fc2, p_x2, out, nullptr, N_TOK, C_DIM, 4 * C_DIM);
}

// round 6
// speedup vs baseline: 5.5306x; 1.5014x over previous
#include <cuda_runtime.h>
#include <cuda_fp16.h>
#include <math.h>
#include <stdint.h>

// Problem constants
#define B_SZ   2
#define T_SEQ  2048
#define C_DIM  1024
#define NH     16
#define HDIM   64
#define N_TOK  (B_SZ * T_SEQ)   // 4096

// ---------------------------------------------------------------------------
// Scratch (device globals; runtime alloc is forbidden)
// ---------------------------------------------------------------------------
__device__ float  g_x2_buf[N_TOK * C_DIM];          // x after attn residual
__device__ __half g_a16[N_TOK * C_DIM];             // LN out (fp16, reused)
__device__ __half g_y16[N_TOK * C_DIM];             // attn out (fp16)
__device__ __half g_m16[N_TOK * 4 * C_DIM];         // gelu act (fp16)
// Q/K/V head-major planes [(b*NH+h)][t][64]. Q pre-scaled by 1/8.
__device__ __half g_q16[N_TOK * C_DIM];
__device__ __half g_k16[N_TOK * C_DIM];
__device__ __half g_v16[N_TOK * C_DIM];
// Transposed weights: Wt[n*K + k] = W[k*N + n]
__device__ __half g_wattn16[3 * C_DIM * C_DIM];
__device__ __half g_wproj16[C_DIM * C_DIM];
__device__ __half g_wfc16  [4 * C_DIM * C_DIM];
__device__ __half g_wfc216 [C_DIM * 4 * C_DIM];

// ---------------------------------------------------------------------------
// Helpers
// ---------------------------------------------------------------------------
__device__ __forceinline__ float gelu_tanh(float v) {
    float v3 = v * v * v;
    return 0.5f * v * (1.0f + tanhf(0.7978845608028654f * (v + 0.044715f * v3)));
}

// Fast exp on the FMA pipe (no MUFU). Valid for x <= 0 (softmax args).
__device__ __forceinline__ float fexp(float x) {
    float t = fmaxf(x * 1.4426950408889634f, -126.0f);
    float fi = t + 12582912.0f;
    int   ii = __float_as_int(fi) - 0x4B400000;
    float f  = t - (fi - 12582912.0f);
    float p  = 1.3333558146e-3f;
    p = fmaf(p, f, 9.6181291056e-3f);
    p = fmaf(p, f, 5.5504108664e-2f);
    p = fmaf(p, f, 2.4022650696e-1f);
    p = fmaf(p, f, 6.9314718056e-1f);
    p = fmaf(p, f, 1.0f);
    return __int_as_float((ii + 127) << 23) * p;
}

__device__ __forceinline__ uint32_t smem_u32(const void* p) {
    uint32_t a;
    asm("{ .reg .u64 t; cvta.to.shared.u64 t, %1; cvt.u32.u64 %0, t; }" : "=r"(a) : "l"(p));
    return a;
}

__device__ __forceinline__ void ldm_x4(uint32_t* r, uint32_t addr) {
    asm volatile("ldmatrix.sync.aligned.m8n8.x4.shared.b16 {%0,%1,%2,%3}, [%4];"
                 : "=r"(r[0]), "=r"(r[1]), "=r"(r[2]), "=r"(r[3]) : "r"(addr));
}

__device__ __forceinline__ void ldm_x4t(uint32_t* r, uint32_t addr) {
    asm volatile("ldmatrix.sync.aligned.m8n8.x4.trans.shared.b16 {%0,%1,%2,%3}, [%4];"
                 : "=r"(r[0]), "=r"(r[1]), "=r"(r[2]), "=r"(r[3]) : "r"(addr));
}

__device__ __forceinline__ void mma_f16(float* c, const uint32_t* a, const uint32_t* b) {
    asm volatile(
        "mma.sync.aligned.m16n8k16.row.col.f32.f16.f16.f32 "
        "{%0,%1,%2,%3}, {%4,%5,%6,%7}, {%8,%9}, {%0,%1,%2,%3};"
        : "+f"(c[0]), "+f"(c[1]), "+f"(c[2]), "+f"(c[3])
        : "r"(a[0]), "r"(a[1]), "r"(a[2]), "r"(a[3]), "r"(b[0]), "r"(b[1]));
}

__device__ __forceinline__ void cp16(uint32_t saddr, const void* g) {
    asm volatile("cp.async.cg.shared.global [%0], [%1], 16;" :: "r"(saddr), "l"(g));
}
#define CP_COMMIT() asm volatile("cp.async.commit_group;")
#define CP_WAIT(n)  asm volatile("cp.async.wait_group %0;" :: "n"(n))

__device__ __forceinline__ uint32_t pack_h2(float a, float b) {
    __half2 t = __floats2half2_rn(a, b);
    return *reinterpret_cast<uint32_t*>(&t);
}

// GEMM smem tile geometry: 128 rows x 32 fp16, row stride 40 elems (80 B)
#define T_STRIDE   40
#define T_ROWB     80
#define T_BYTES    10240
#define BUF2_BYTES (2 * T_BYTES)
#define GEMM_SMEM16 (2 * BUF2_BYTES)     // 40960

// ---------------------------------------------------------------------------
// Weight transpose -> fp16
// ---------------------------------------------------------------------------
__global__ __launch_bounds__(256) void transpose_f16_kernel(
    const float* __restrict__ W, __half* __restrict__ T16, int K, int N)
{
    __shared__ float t[32][33];
    int n0 = blockIdx.x * 32, k0 = blockIdx.y * 32;
    int tx = threadIdx.x, ty = threadIdx.y;
    #pragma unroll
    for (int i = 0; i < 4; i++)
        t[ty + 8 * i][tx] = W[(size_t)(k0 + ty + 8 * i) * N + n0 + tx];
    __syncthreads();
    #pragma unroll
    for (int i = 0; i < 4; i++) {
        size_t o = (size_t)(n0 + ty + 8 * i) * K + k0 + tx;
        T16[o] = __float2half_rn(t[tx][ty + 8 * i]);
    }
}

// ---------------------------------------------------------------------------
// LayerNorm -> fp16
// ---------------------------------------------------------------------------
__global__ __launch_bounds__(256) void ln_kernel(
    const float* __restrict__ x, const float* __restrict__ g,
    const float* __restrict__ b, __half* __restrict__ o16)
{
    __shared__ float red[8];
    int row = blockIdx.x;
    int tid = threadIdx.x;
    const float4* x4 = (const float4*)(x + (size_t)row * C_DIM);
    float4 v = x4[tid];

    float s = v.x + v.y + v.z + v.w;
    #pragma unroll
    for (int o = 16; o; o >>= 1) s += __shfl_xor_sync(0xffffffffu, s, o);
    if ((tid & 31) == 0) red[tid >> 5] = s;
    __syncthreads();
    s = red[0] + red[1] + red[2] + red[3] + red[4] + red[5] + red[6] + red[7];
    float mu = s * (1.0f / C_DIM);

    float dx0 = v.x - mu, dx1 = v.y - mu, dx2 = v.z - mu, dx3 = v.w - mu;
    float q = dx0*dx0 + dx1*dx1 + dx2*dx2 + dx3*dx3;
    #pragma unroll
    for (int o = 16; o; o >>= 1) q += __shfl_xor_sync(0xffffffffu, q, o);
    __syncthreads();
    if ((tid & 31) == 0) red[tid >> 5] = q;
    __syncthreads();
    q = red[0] + red[1] + red[2] + red[3] + red[4] + red[5] + red[6] + red[7];
    float rs = rsqrtf(q * (1.0f / C_DIM) + 1e-5f);

    float4 gg = ((const float4*)g)[tid];
    float4 bb = ((const float4*)b)[tid];
    float o0 = dx0 * rs * gg.x + bb.x;
    float o1 = dx1 * rs * gg.y + bb.y;
    float o2 = dx2 * rs * gg.z + bb.z;
    float o3 = dx3 * rs * gg.w + bb.w;

    size_t base = (size_t)row * C_DIM + tid * 4;
    ((__half2*)(o16 + base))[0] = __floats2half2_rn(o0, o1);
    ((__half2*)(o16 + base))[1] = __floats2half2_rn(o2, o3);
}

// ---------------------------------------------------------------------------
// fp16 1-pass HMMA GEMM: D = A[M,K] @ B[N,K]^T.
// EPI 1: fp32 out + bias + res. EPI 2: gelu -> fp16. EPI 3: qkv -> head planes.
// ---------------------------------------------------------------------------
template<int EPI>
__global__ __launch_bounds__(256) void hmma_gemm_f16(
    const __half* __restrict__ A, const __half* __restrict__ B,
    const float* __restrict__ bias, const float* __restrict__ res,
    float* __restrict__ outf, __half* __restrict__ o16,
    __half* __restrict__ q16, __half* __restrict__ k16, __half* __restrict__ v16,
    int M, int N, int K)
{
    extern __shared__ char smem[];
    uint32_t sb = smem_u32(smem);
    int tid = threadIdx.x, lane = tid & 31, w = tid >> 5;
    int wm = w >> 2, wn = w & 3;
    int m0 = blockIdx.y * 128, n0 = blockIdx.x * 128;

    const __half* srcs[2] = { A + (size_t)m0 * K, B + (size_t)n0 * K };

    float acc[4][4][4];
    #pragma unroll
    for (int a = 0; a < 4; a++)
        #pragma unroll
        for (int b = 0; b < 4; b++)
            #pragma unroll
            for (int c = 0; c < 4; c++) acc[a][b][c] = 0.0f;

    const int nch = K >> 5;

    #pragma unroll
    for (int t = 0; t < 2; t++) {
        #pragma unroll
        for (int u = 0; u < 2; u++) {
            int idx = tid + 256 * u;
            int r = idx >> 2, c = idx & 3;
            cp16(sb + t * T_BYTES + r * T_ROWB + c * 16, srcs[t] + (size_t)r * K + c * 8);
        }
    }
    CP_COMMIT();

    for (int ch = 0; ch < nch; ch++) {
        uint32_t buf = sb + (ch & 1) * BUF2_BYTES;
        if (ch + 1 < nch) {
            uint32_t nbuf = sb + ((ch + 1) & 1) * BUF2_BYTES;
            int k0 = (ch + 1) << 5;
            #pragma unroll
            for (int t = 0; t < 2; t++) {
                #pragma unroll
                for (int u = 0; u < 2; u++) {
                    int idx = tid + 256 * u;
                    int r = idx >> 2, c = idx & 3;
                    cp16(nbuf + t * T_BYTES + r * T_ROWB + c * 16,
                         srcs[t] + (size_t)r * K + k0 + c * 8);
                }
            }
            CP_COMMIT();
            CP_WAIT(1);
        } else {
            CP_WAIT(0);
        }
        __syncthreads();

        uint32_t abase = buf;
        uint32_t bbase = buf + T_BYTES;
        int arow = (lane & 7) + ((lane >> 3) & 1) * 8;
        int akof = ((lane >> 4) & 1) * 8;
        int brow = (lane & 7) + ((lane >> 4) & 1) * 8;
        int bkof = ((lane >> 3) & 1) * 8;

        #pragma unroll
        for (int ks = 0; ks < 2; ks++) {
            uint32_t Af[4][4], Bf[4][2];
            #pragma unroll
            for (int mf = 0; mf < 4; mf++) {
                uint32_t ad = abase + (uint32_t)(((wm * 64 + mf * 16 + arow) * T_STRIDE
                                                 + ks * 16 + akof) * 2);
                ldm_x4(Af[mf], ad);
            }
            #pragma unroll
            for (int np = 0; np < 2; np++) {
                uint32_t bd = bbase + (uint32_t)(((wn * 32 + np * 16 + brow) * T_STRIDE
                                                 + ks * 16 + bkof) * 2);
                uint32_t th[4];
                ldm_x4(th, bd);
                Bf[np*2][0]=th[0]; Bf[np*2][1]=th[1]; Bf[np*2+1][0]=th[2]; Bf[np*2+1][1]=th[3];
            }
            #pragma unroll
            for (int mf = 0; mf < 4; mf++)
                #pragma unroll
                for (int nf = 0; nf < 4; nf++)
                    mma_f16(acc[mf][nf], Af[mf], Bf[nf]);
        }
        __syncthreads();
    }

    int qr = lane >> 2;
    int qc = (lane & 3) * 2;
    #pragma unroll
    for (int mf = 0; mf < 4; mf++) {
        #pragma unroll
        for (int nf = 0; nf < 4; nf++) {
            int col = n0 + wn * 32 + nf * 8 + qc;
            float b0 = bias[col], b1 = bias[col + 1];
            #pragma unroll
            for (int half = 0; half < 2; half++) {
                int row = m0 + wm * 64 + mf * 16 + qr + half * 8;
                float v0 = acc[mf][nf][half * 2 + 0] + b0;
                float v1 = acc[mf][nf][half * 2 + 1] + b1;
                if (EPI == 1) {
                    size_t gi = (size_t)row * N + col;
                    float2 rv = *(const float2*)(res + gi);
                    v0 += rv.x; v1 += rv.y;
                    *(float2*)(outf + gi) = make_float2(v0, v1);
                } else if (EPI == 2) {
                    size_t gi = (size_t)row * N + col;
                    v0 = gelu_tanh(v0);
                    v1 = gelu_tanh(v1);
                    *(__half2*)(o16 + gi) = __floats2half2_rn(v0, v1);
                } else {
                    int sec = col >> 10;
                    int within = col & 1023;
                    int hd = within >> 6, d = within & 63;
                    if (sec == 0) { v0 *= 0.125f; v1 *= 0.125f; }
                    size_t gi = ((size_t)((row >> 11) * NH + hd) * T_SEQ + (row & 2047)) * 64 + d;
                    __half* dst = (sec == 0) ? q16 : (sec == 1) ? k16 : v16;
                    *(__half2*)(dst + gi) = __floats2half2_rn(v0, v1);
                }
            }
        }
    }
}

// ---------------------------------------------------------------------------
// Flash attention, fp16 HMMA 1-pass, causal, HD=64.
// q-tile 128 (8 warps x m16), kv-tile 64, cp.async double-buffered K/V.
// ---------------------------------------------------------------------------
#define FQT   144                      // smem row pitch bytes (64 fp16 + pad)
#define FQSZ  (128 * FQT)              // Q tile = 18432
#define FTSZ  (64 * FQT)               // one 64-row tile = 9216
#define FKVSZ (2 * FTSZ)               // K, V = 18432
#define FLASH_SMEM (FQSZ + 2 * FKVSZ)  // 55296

__global__ __launch_bounds__(256) void flash_hmma(
    const __half* __restrict__ q16, const __half* __restrict__ k16,
    const __half* __restrict__ v16, __half* __restrict__ y16)
{
    extern __shared__ char smf[];
    uint32_t sb = smem_u32(smf);
    int tid = threadIdx.x, lane = tid & 31, w = tid >> 5;
    int bh = blockIdx.y;
    int qb = blockIdx.x * 128;
    size_t plane = (size_t)bh * (T_SEQ * 64);

    const __half* qsrc = q16 + plane + (size_t)qb * 64;
    const __half* ks[2] = { k16 + plane, v16 + plane };

    // Q tile via cp.async: 128 rows x 128 B
    #pragma unroll
    for (int u = 0; u < 4; u++) {
        int idx = tid + 256 * u;
        int r = idx >> 3, c = idx & 7;
        cp16(sb + r * FQT + c * 16, qsrc + (size_t)r * 64 + c * 8);
    }
    CP_COMMIT();
    // KV tile 0 -> buffer 0
    #pragma unroll
    for (int u = 0; u < 4; u++) {
        int idx = tid + 256 * u;
        int t = idx >> 9, r = (idx >> 3) & 63, c = idx & 7;
        cp16(sb + FQSZ + t * FTSZ + r * FQT + c * 16, ks[t] + (size_t)r * 64 + c * 8);
    }
    CP_COMMIT();
    CP_WAIT(1);
    __syncthreads();

    // Q fragments held in registers
    int arow = (lane & 7) + ((lane >> 3) & 1) * 8;
    int akof = ((lane >> 4) & 1) * 8;
    uint32_t Qf[4][4];
    #pragma unroll
    for (int kc = 0; kc < 4; kc++) {
        uint32_t ad = sb + (uint32_t)((w * 16 + arow) * FQT + (kc * 16 + akof) * 2);
        ldm_x4(Qf[kc], ad);
    }

    float oacc[8][4];
    #pragma unroll
    for (int j = 0; j < 8; j++)
        #pragma unroll
        for (int c = 0; c < 4; c++) oacc[j][c] = 0.0f;
    float m_run[2] = { -1e30f, -1e30f };
    float l_run[2] = { 0.0f, 0.0f };

    int brow = (lane & 7) + ((lane >> 4) & 1) * 8;
    int bkof = ((lane >> 3) & 1) * 8;
    int vrow = (lane & 7) + ((lane >> 3) & 1) * 8;
    int vcol = ((lane >> 4) & 1) * 8;

    const int nkv = (qb >> 6) + 2;
    for (int it = 0; it < nkv; it++) {
        if (it + 1 < nkv) {
            int kb2 = (it + 1) << 6;
            uint32_t nb_ = sb + FQSZ + ((it + 1) & 1) * FKVSZ;
            #pragma unroll
            for (int u = 0; u < 4; u++) {
                int idx = tid + 256 * u;
                int t = idx >> 9, r = (idx >> 3) & 63, c = idx & 7;
                cp16(nb_ + t * FTSZ + r * FQT + c * 16, ks[t] + (size_t)(kb2 + r) * 64 + c * 8);
            }
            CP_COMMIT();
            CP_WAIT(1);
        } else {
            CP_WAIT(0);
        }
        __syncthreads();
        uint32_t kvb = sb + FQSZ + (it & 1) * FKVSZ;

        // ---- S = Q K^T ----
        float sacc[8][4];
        #pragma unroll
        for (int j = 0; j < 8; j++)
            #pragma unroll
            for (int c = 0; c < 4; c++) sacc[j][c] = 0.0f;

        #pragma unroll
        for (int kc = 0; kc < 4; kc++) {
            #pragma unroll
            for (int nb2 = 0; nb2 < 4; nb2++) {
                uint32_t ad = kvb + (uint32_t)((nb2 * 16 + brow) * FQT + (kc * 16 + bkof) * 2);
                uint32_t th[4];
                ldm_x4(th, ad);
                uint32_t b0[2] = { th[0], th[1] }, b1[2] = { th[2], th[3] };
                mma_f16(sacc[nb2*2],   Qf[kc], b0);
                mma_f16(sacc[nb2*2+1], Qf[kc], b1);
            }
        }

        // ---- causal mask ----
        int kb = it << 6;
        int qrow = qb + w * 16 + (lane >> 2);
        if (kb + 63 > qb + w * 16) {
            #pragma unroll
            for (int j = 0; j < 8; j++) {
                int col = kb + j * 8 + (lane & 3) * 2;
                #pragma unroll
                for (int rh = 0; rh < 2; rh++) {
                    int row = qrow + rh * 8;
                    if (col     > row) sacc[j][rh*2]   = -1e30f;
                    if (col + 1 > row) sacc[j][rh*2+1] = -1e30f;
                }
            }
        }

        // ---- online softmax ----
        #pragma unroll
        for (int rh = 0; rh < 2; rh++) {
            float mt = -1e30f;
            #pragma unroll
            for (int j = 0; j < 8; j++) {
                mt = fmaxf(mt, sacc[j][rh*2]);
                mt = fmaxf(mt, sacc[j][rh*2+1]);
            }
            mt = fmaxf(mt, __shfl_xor_sync(0xffffffffu, mt, 1));
            mt = fmaxf(mt, __shfl_xor_sync(0xffffffffu, mt, 2));
            float m_new = fmaxf(m_run[rh], mt);
            float alpha = fexp(m_run[rh] - m_new);
            m_run[rh] = m_new;
            float sum = 0.0f;
            #pragma unroll
            for (int j = 0; j < 8; j++) {
                float p0 = fexp(sacc[j][rh*2]   - m_new);
                float p1 = fexp(sacc[j][rh*2+1] - m_new);
                sacc[j][rh*2]   = p0;
                sacc[j][rh*2+1] = p1;
                sum += p0 + p1;
            }
            sum += __shfl_xor_sync(0xffffffffu, sum, 1);
            sum += __shfl_xor_sync(0xffffffffu, sum, 2);
            l_run[rh] = l_run[rh] * alpha + sum;
            #pragma unroll
            for (int j = 0; j < 8; j++) {
                oacc[j][rh*2]   *= alpha;
                oacc[j][rh*2+1] *= alpha;
            }
        }

        // ---- pack P into A fragments ----
        uint32_t Pf[4][4];
        #pragma unroll
        for (int kc = 0; kc < 4; kc++) {
            #pragma unroll
            for (int q4 = 0; q4 < 4; q4++) {
                int j  = kc * 2 + (q4 >> 1);
                int rh = q4 & 1;
                Pf[kc][q4] = pack_h2(sacc[j][rh*2], sacc[j][rh*2+1]);
            }
        }

        // ---- O += P V ----
        #pragma unroll
        for (int kc = 0; kc < 4; kc++) {
            #pragma unroll
            for (int nb2 = 0; nb2 < 4; nb2++) {
                uint32_t ad = kvb + FTSZ
                            + (uint32_t)((kc * 16 + vrow) * FQT + (nb2 * 16 + vcol) * 2);
                uint32_t th[4];
                ldm_x4t(th, ad);
                uint32_t b0[2] = { th[0], th[1] }, b1[2] = { th[2], th[3] };
                mma_f16(oacc[nb2*2],   Pf[kc], b0);
                mma_f16(oacc[nb2*2+1], Pf[kc], b1);
            }
        }
        __syncthreads();
    }

    // ---- epilogue ----
    float inv0 = 1.0f / l_run[0];
    float inv1 = 1.0f / l_run[1];
    int b = bh >> 4, h = bh & 15;
    #pragma unroll
    for (int j = 0; j < 8; j++) {
        #pragma unroll
        for (int rh = 0; rh < 2; rh++) {
            float iv = rh ? inv1 : inv0;
            float o0 = oacc[j][rh*2]   * iv;
            float o1 = oacc[j][rh*2+1] * iv;
            size_t row = (size_t)b * T_SEQ + qb + w * 16 + (lane >> 2) + rh * 8;
            size_t gi = row * C_DIM + h * 64 + j * 8 + (lane & 3) * 2;
            *(__half2*)(y16 + gi) = __floats2half2_rn(o0, o1);
        }
    }
}

// ---------------------------------------------------------------------------
// Launch
// ---------------------------------------------------------------------------
extern "C" void kernel_launch(void* const* d_in, const int* in_sizes, int n_in,
                              void* d_out, int out_size)
{
    const float* x      = (const float*)d_in[0];
    const float* ln1_g  = (const float*)d_in[1];
    const float* ln1_b  = (const float*)d_in[2];
    const float* W_attn = (const float*)d_in[3];
    const float* b_attn = (const float*)d_in[4];
    const float* W_proj = (const float*)d_in[5];
    const float* b_proj = (const float*)d_in[6];
    const float* ln2_g  = (const float*)d_in[7];
    const float* ln2_b  = (const float*)d_in[8];
    const float* W_fc   = (const float*)d_in[9];
    const float* b_fc   = (const float*)d_in[10];
    const float* W_fc2  = (const float*)d_in[11];
    const float* b_fc2  = (const float*)d_in[12];
    float* out = (float*)d_out;

    float *p_x2;
    __half *p_a16, *p_y16, *p_m16, *p_q16, *p_k16, *p_v16;
    __half *p_wa16, *p_wp16, *p_wf16, *p_w216;
    cudaGetSymbolAddress((void**)&p_x2,  g_x2_buf);
    cudaGetSymbolAddress((void**)&p_a16, g_a16);
    cudaGetSymbolAddress((void**)&p_y16, g_y16);
    cudaGetSymbolAddress((void**)&p_m16, g_m16);
    cudaGetSymbolAddress((void**)&p_q16, g_q16);
    cudaGetSymbolAddress((void**)&p_k16, g_k16);
    cudaGetSymbolAddress((void**)&p_v16, g_v16);
    cudaGetSymbolAddress((void**)&p_wa16, g_wattn16);
    cudaGetSymbolAddress((void**)&p_wp16, g_wproj16);
    cudaGetSymbolAddress((void**)&p_wf16, g_wfc16);
    cudaGetSymbolAddress((void**)&p_w216, g_wfc216);

    cudaFuncSetAttribute(flash_hmma, cudaFuncAttributeMaxDynamicSharedMemorySize, FLASH_SMEM);
    cudaFuncSetAttribute(hmma_gemm_f16<1>, cudaFuncAttributeMaxDynamicSharedMemorySize, GEMM_SMEM16);
    cudaFuncSetAttribute(hmma_gemm_f16<2>, cudaFuncAttributeMaxDynamicSharedMemorySize, GEMM_SMEM16);
    cudaFuncSetAttribute(hmma_gemm_f16<3>, cudaFuncAttributeMaxDynamicSharedMemorySize, GEMM_SMEM16);

    dim3 tb(32, 8);
    transpose_f16_kernel<<<dim3(3 * C_DIM / 32, C_DIM / 32), tb>>>(W_attn, p_wa16, C_DIM, 3 * C_DIM);
    transpose_f16_kernel<<<dim3(C_DIM / 32, C_DIM / 32), tb>>>(W_proj, p_wp16, C_DIM, C_DIM);
    transpose_f16_kernel<<<dim3(4 * C_DIM / 32, C_DIM / 32), tb>>>(W_fc, p_wf16, C_DIM, 4 * C_DIM);
    transpose_f16_kernel<<<dim3(C_DIM / 32, 4 * C_DIM / 32), tb>>>(W_fc2, p_w216, 4 * C_DIM, C_DIM);

    // 1. LN1 -> fp16
    ln_kernel<<<N_TOK, 256>>>(x, ln1_g, ln1_b, p_a16);
    // 2. QKV GEMM (fp16 1-pass) -> head-major q/k/v planes (q pre-scaled)
    hmma_gemm_f16<3><<<dim3(3 * C_DIM / 128, N_TOK / 128), 256, GEMM_SMEM16>>>(
        p_a16, p_wa16, b_attn, nullptr, nullptr, nullptr,
        p_q16, p_k16, p_v16, N_TOK, 3 * C_DIM, C_DIM);
    // 3. Flash attention (fp16 1-pass) -> y fp16
    flash_hmma<<<dim3(T_SEQ / 128, B_SZ * NH), 256, FLASH_SMEM>>>(
        p_q16, p_k16, p_v16, p_y16);
    // 4. Proj GEMM + residual -> x2 fp32
    hmma_gemm_f16<1><<<dim3(C_DIM / 128, N_TOK / 128), 256, GEMM_SMEM16>>>(
        p_y16, p_wp16, b_proj, x, p_x2, nullptr,
        nullptr, nullptr, nullptr, N_TOK, C_DIM, C_DIM);
    // 5. LN2 -> fp16
    ln_kernel<<<N_TOK, 256>>>(p_x2, ln2_g, ln2_b, p_a16);
    // 6. FC GEMM + GELU -> fp16 act
    hmma_gemm_f16<2><<<dim3(4 * C_DIM / 128, N_TOK / 128), 256, GEMM_SMEM16>>>(
        p_a16, p_wf16, b_fc, nullptr, nullptr, p_m16,
        nullptr, nullptr, nullptr, N_TOK, 4 * C_DIM, C_DIM);
    // 7. FC2 GEMM + residual -> final out
    hmma_gemm_f16<1><<<dim3(C_DIM / 128, N_TOK / 128), 256, GEMM_SMEM16>>>(
        p_m16, p_w216, b_fc2, p_x2, out, nullptr,
        nullptr, nullptr, nullptr, N_TOK, C_DIM, 4 * C_DIM);
}